// round 1
// baseline (speedup 1.0000x reference)
#include <cuda_runtime.h>
#include <math.h>

#define Bc 2
#define Nc 1536
#define Dc 1024
#define Hc 16
#define DHc 64
#define Mc (Bc*Nc)

// Scratch (allocation-free rule: device globals)
__device__ float g_Q[Bc*Hc*Nc*DHc];
__device__ float g_K[Bc*Hc*Nc*DHc];
__device__ float g_V[Bc*Hc*Nc*DHc];
__device__ float g_G1[Mc*Dc];
__device__ float g_attnO[Mc*Dc];
__device__ float g_gate[Mc];

// ---------------------------------------------------------------------------
// Tiled SGEMM: C[M,1024] = A[M,1024] @ W[1024,1024] (+bias), 64x64 tile, 4x4/thr
// MODE 0: plain row-major out
// MODE 1: scatter to [B,H,N,DH] layout, scaled (for Q/K/V)
// MODE 2: exact GELU epilogue (for gate MLP hidden)
// ---------------------------------------------------------------------------
template<int MODE>
__global__ void gemm_k(const float* __restrict__ A, const float* __restrict__ W,
                       const float* __restrict__ bias, float* __restrict__ C,
                       float scale)
{
    __shared__ float As[16][64];   // A tile, transposed: As[k][m]
    __shared__ float Bs[16][64];   // W tile: Bs[k][n]
    const int tid = threadIdx.x;
    const int tx = tid & 15, ty = tid >> 4;
    const int bx = blockIdx.x, by = blockIdx.y;

    float acc[4][4];
    #pragma unroll
    for (int i = 0; i < 4; i++)
        #pragma unroll
        for (int j = 0; j < 4; j++) acc[i][j] = 0.f;

    const int lr  = tid >> 2;        // 0..63 : A tile row
    const int lc4 = (tid & 3) * 4;   // 0,4,8,12 : k-offset within 16-wide tile
    const float* Arow = A + (size_t)(by*64 + lr)*Dc;
    const int brow = tid >> 4;       // 0..15 : k row of W tile
    const int bcol = (tid & 15)*4;

    for (int kk = 0; kk < Dc; kk += 16) {
        float4 a4 = *(const float4*)(Arow + kk + lc4);
        As[lc4+0][lr] = a4.x;
        As[lc4+1][lr] = a4.y;
        As[lc4+2][lr] = a4.z;
        As[lc4+3][lr] = a4.w;
        *(float4*)&Bs[brow][bcol] =
            *(const float4*)&W[(size_t)(kk + brow)*Dc + bx*64 + bcol];
        __syncthreads();
        #pragma unroll
        for (int k = 0; k < 16; k++) {
            float4 av = *(float4*)&As[k][ty*4];
            float4 bv = *(float4*)&Bs[k][tx*4];
            float ar[4] = {av.x, av.y, av.z, av.w};
            float br[4] = {bv.x, bv.y, bv.z, bv.w};
            #pragma unroll
            for (int i = 0; i < 4; i++)
                #pragma unroll
                for (int j = 0; j < 4; j++)
                    acc[i][j] += ar[i]*br[j];
        }
        __syncthreads();
    }

    #pragma unroll
    for (int i = 0; i < 4; i++) {
        const int r = by*64 + ty*4 + i;
        #pragma unroll
        for (int j = 0; j < 4; j++) {
            const int c = bx*64 + tx*4 + j;
            float v = acc[i][j] + bias[c];
            if (MODE == 0) {
                C[(size_t)r*Dc + c] = v;
            } else if (MODE == 1) {
                v *= scale;
                const int b = r / Nc, n = r % Nc;
                const int h = c >> 6, dh = c & 63;
                C[(((size_t)(b*Hc + h))*Nc + n)*DHc + dh] = v;
            } else {
                // exact GELU: 0.5*v*(1+erf(v/sqrt(2)))
                C[(size_t)r*Dc + c] = 0.5f*v*(1.f + erff(v*0.70710678118654752f));
            }
        }
    }
}

// ---------------------------------------------------------------------------
// Gate: gate[r] = sigmoid( dot(G1[r,:], Wg2) + bg2 )
// ---------------------------------------------------------------------------
__global__ void gate_k(const float* __restrict__ G1, const float* __restrict__ Wg2,
                       const float* __restrict__ bg2, float* __restrict__ gate)
{
    __shared__ float red[256];
    const int r = blockIdx.x;
    float s = 0.f;
    for (int k = threadIdx.x; k < Dc; k += 256)
        s += G1[(size_t)r*Dc + k] * Wg2[k];
    red[threadIdx.x] = s;
    __syncthreads();
    for (int o = 128; o; o >>= 1) {
        if (threadIdx.x < o) red[threadIdx.x] += red[threadIdx.x + o];
        __syncthreads();
    }
    if (threadIdx.x == 0) {
        float z = red[0] + bg2[0];
        gate[r] = 1.f / (1.f + expf(-z));
    }
}

// ---------------------------------------------------------------------------
// Causal attention + exact entropy + gate, one warp per query row.
// Q is pre-scaled by DH^-0.5 in the projection epilogue.
// Scores for a row live in smem; softmax'd in place; reused for P@V.
// ---------------------------------------------------------------------------
__global__ void attn_k(const float* __restrict__ Q, const float* __restrict__ Kg,
                       const float* __restrict__ Vg, const float* __restrict__ gate,
                       float* __restrict__ O, float* __restrict__ ent)
{
    extern __shared__ float sm[];
    float* S  = sm;                 // 8 * 1536 scores (then probabilities)
    float* Kt = sm + 8*Nc;          // 64 x 65 K/V tile (padded)
    float* Qs = Kt + 64*65;         // 8 x 64 query rows

    const int tid  = threadIdx.x;
    const int w    = tid >> 5;
    const int lane = tid & 31;
    const int nqb  = Nc / 8;
    const int bh   = blockIdx.x / nqb;
    const int q0   = (blockIdx.x % nqb) * 8;
    const int q    = q0 + w;

    const float* Qb = Q  + (size_t)bh*Nc*DHc;
    const float* Kb = Kg + (size_t)bh*Nc*DHc;
    const float* Vb = Vg + (size_t)bh*Nc*DHc;

    for (int i = tid; i < 8*DHc; i += 256)
        Qs[i] = Qb[(size_t)q0*DHc + i];

    const int ntiles = (q0 + 7) / 64 + 1;
    float* Sw = S + w*Nc;

    // Pass 1: S = Q @ K^T (causal: only j <= q)
    for (int t = 0; t < ntiles; t++) {
        const int t0 = t*64;
        __syncthreads();
        for (int i = tid; i < 64*64; i += 256)
            Kt[(i >> 6)*65 + (i & 63)] = Kb[(size_t)t0*DHc + i];
        __syncthreads();
        #pragma unroll
        for (int jj = lane; jj < 64; jj += 32) {
            const int j = t0 + jj;
            if (j <= q) {
                float s = 0.f;
                const float* qp = Qs + w*DHc;
                const float* kp = Kt + jj*65;
                #pragma unroll
                for (int k = 0; k < 64; k++) s += qp[k]*kp[k];
                Sw[j] = s;
            }
        }
    }

    // Softmax stats, exact probabilities, entropy
    float m = -1e30f;
    for (int j = lane; j <= q; j += 32) m = fmaxf(m, Sw[j]);
    #pragma unroll
    for (int o = 16; o; o >>= 1) m = fmaxf(m, __shfl_xor_sync(0xffffffffu, m, o));
    float l = 0.f;
    for (int j = lane; j <= q; j += 32) l += __expf(Sw[j] - m);
    #pragma unroll
    for (int o = 16; o; o >>= 1) l += __shfl_xor_sync(0xffffffffu, l, o);
    const float inv = 1.f / l;
    float e = 0.f;
    for (int j = lane; j <= q; j += 32) {
        float p = __expf(Sw[j] - m) * inv;
        Sw[j] = p;
        e -= p * __logf(p + 1e-6f);
    }
    #pragma unroll
    for (int o = 16; o; o >>= 1) e += __shfl_xor_sync(0xffffffffu, e, o);

    // Pass 2: acc = P @ V  (lane owns dh = lane, lane+32)
    float a0 = 0.f, a1 = 0.f;
    for (int t = 0; t < ntiles; t++) {
        const int t0 = t*64;
        __syncthreads();
        for (int i = tid; i < 64*64; i += 256)
            Kt[(i >> 6)*65 + (i & 63)] = Vb[(size_t)t0*DHc + i];
        __syncthreads();
        const int jend = min(63, q - t0);
        for (int jl = 0; jl <= jend; jl++) {
            const float p = Sw[t0 + jl];
            a0 += p * Kt[jl*65 + lane];
            a1 += p * Kt[jl*65 + 32 + lane];
        }
    }

    const int b = bh / Hc, h = bh % Hc;
    const float g = gate[(size_t)b*Nc + q];
    O[((size_t)b*Nc + q)*Dc + h*DHc + lane]      = a0 * g;
    O[((size_t)b*Nc + q)*Dc + h*DHc + 32 + lane] = a1 * g;
    if (lane == 0) ent[(size_t)bh*Nc + q] = e;
}

// ---------------------------------------------------------------------------
extern "C" void kernel_launch(void* const* d_in, const int* in_sizes, int n_in,
                              void* d_out, int out_size)
{
    const float* x   = (const float*)d_in[0];
    // d_in[1] = attn_bias (pure causal mask; handled analytically)
    const float* Wq  = (const float*)d_in[2];
    const float* bq  = (const float*)d_in[3];
    const float* Wk  = (const float*)d_in[4];
    const float* bk  = (const float*)d_in[5];
    const float* Wv  = (const float*)d_in[6];
    const float* bv  = (const float*)d_in[7];
    const float* Wg1 = (const float*)d_in[8];
    const float* bg1 = (const float*)d_in[9];
    const float* Wg2 = (const float*)d_in[10];
    const float* bg2 = (const float*)d_in[11];
    const float* Wo  = (const float*)d_in[12];
    const float* bo  = (const float*)d_in[13];

    float* out = (float*)d_out;                       // [B, N, D]
    float* ent = out + (size_t)Bc*Nc*Dc;              // [B, H, N]

    float *Qp, *Kp, *Vp, *G1p, *AOp, *Gp;
    cudaGetSymbolAddress((void**)&Qp,  g_Q);
    cudaGetSymbolAddress((void**)&Kp,  g_K);
    cudaGetSymbolAddress((void**)&Vp,  g_V);
    cudaGetSymbolAddress((void**)&G1p, g_G1);
    cudaGetSymbolAddress((void**)&AOp, g_attnO);
    cudaGetSymbolAddress((void**)&Gp,  g_gate);

    dim3 gg(Dc/64, Mc/64);
    gemm_k<1><<<gg, 256>>>(x, Wq, bq, Qp, 0.125f);    // Q, pre-scaled by DH^-0.5
    gemm_k<1><<<gg, 256>>>(x, Wk, bk, Kp, 1.f);
    gemm_k<1><<<gg, 256>>>(x, Wv, bv, Vp, 1.f);
    gemm_k<2><<<gg, 256>>>(x, Wg1, bg1, G1p, 1.f);    // GELU hidden
    gate_k<<<Mc, 256>>>(G1p, Wg2, bg2, Gp);

    const size_t smem = (size_t)(8*Nc + 64*65 + 8*DHc) * sizeof(float);
    cudaFuncSetAttribute(attn_k, cudaFuncAttributeMaxDynamicSharedMemorySize, (int)smem);
    attn_k<<<Bc*Hc*(Nc/8), 256, smem>>>(Qp, Kp, Vp, Gp, AOp, ent);

    gemm_k<0><<<gg, 256>>>(AOp, Wo, bo, out, 1.f);
}

// round 3
// speedup vs baseline: 1.3445x; 1.3445x over previous
#include <cuda_runtime.h>
#include <math.h>

#define Bc 2
#define Nc 1536
#define Dc 1024
#define Hc 16
#define DHc 64
#define Mc (Bc*Nc)
#define BHc (Bc*Hc)
#define QT (Nc/64)
#define PAD 68   // padded row stride (floats): 68*4=272B -> 16B aligned rows

// Scratch (allocation-free rule: device globals)
__device__ float g_Q[BHc*Nc*DHc];
__device__ float g_K[BHc*Nc*DHc];
__device__ float g_V[BHc*Nc*DHc];
__device__ float g_G1[Mc*Dc];
__device__ float g_AO[Mc*Dc];
__device__ float g_gate[Mc];
__device__ float g_S[(size_t)BHc*Nc*Nc];   // 302 MB score scratch
__device__ float g_m[BHc*Nc];
__device__ float g_l[BHc*Nc];

// ---------------------------------------------------------------------------
// SGEMM: C[M,1024] = A[M,1024] @ W[1024,1024] (+bias)
// 128x128 tile, 8x8 per-thread micro-tile, K-step 8, double-buffered smem.
// MODE 0: plain row-major out
// MODE 1: scatter to [B,H,N,DH], scaled (Q/K/V projections)
// MODE 2: exact GELU epilogue (gate MLP hidden)
// ---------------------------------------------------------------------------
template<int MODE>
__global__ void __launch_bounds__(256, 2)
gemm_k(const float* __restrict__ A, const float* __restrict__ W,
       const float* __restrict__ bias, float* __restrict__ C, float scale)
{
    __shared__ float As[2][8][128];   // transposed: As[k][m]
    __shared__ float Bs[2][8][128];   // Bs[k][n]
    const int tid = threadIdx.x;
    const int bx = blockIdx.x, by = blockIdx.y;
    const int tx = tid & 15, ty = tid >> 4;

    const int arow = tid >> 1;          // 0..127
    const int acol = (tid & 1) * 4;     // 0 or 4
    const int brow = tid >> 5;          // 0..7
    const int bcol = (tid & 31) * 4;    // 0..124

    const float* Ap = A + (size_t)(by*128 + arow)*Dc + acol;
    const float* Bp = W + (size_t)brow*Dc + bx*128 + bcol;

    float acc[8][8];
    #pragma unroll
    for (int i = 0; i < 8; i++)
        #pragma unroll
        for (int j = 0; j < 8; j++) acc[i][j] = 0.f;

    // prologue: load tile 0
    {
        float4 a4 = *(const float4*)Ap;
        float4 b4 = *(const float4*)Bp;
        As[0][acol+0][arow] = a4.x;
        As[0][acol+1][arow] = a4.y;
        As[0][acol+2][arow] = a4.z;
        As[0][acol+3][arow] = a4.w;
        *(float4*)&Bs[0][brow][bcol] = b4;
    }
    __syncthreads();

    int buf = 0;
    for (int kk = 8; kk < Dc + 8; kk += 8) {
        float4 a4n, b4n;
        const bool more = (kk < Dc);
        if (more) {
            a4n = *(const float4*)(Ap + kk);
            b4n = *(const float4*)(Bp + (size_t)kk*Dc);
        }
        #pragma unroll
        for (int k = 0; k < 8; k++) {
            float4 x0 = *(float4*)&As[buf][k][ty*8];
            float4 x1 = *(float4*)&As[buf][k][ty*8+4];
            float4 y0 = *(float4*)&Bs[buf][k][tx*8];
            float4 y1 = *(float4*)&Bs[buf][k][tx*8+4];
            float av[8] = {x0.x,x0.y,x0.z,x0.w,x1.x,x1.y,x1.z,x1.w};
            float bv[8] = {y0.x,y0.y,y0.z,y0.w,y1.x,y1.y,y1.z,y1.w};
            #pragma unroll
            for (int i = 0; i < 8; i++)
                #pragma unroll
                for (int j = 0; j < 8; j++)
                    acc[i][j] += av[i]*bv[j];
        }
        if (more) {
            const int nb = buf ^ 1;
            As[nb][acol+0][arow] = a4n.x;
            As[nb][acol+1][arow] = a4n.y;
            As[nb][acol+2][arow] = a4n.z;
            As[nb][acol+3][arow] = a4n.w;
            *(float4*)&Bs[nb][brow][bcol] = b4n;
            __syncthreads();
            buf = nb;
        }
    }

    #pragma unroll
    for (int i = 0; i < 8; i++) {
        const int r = by*128 + ty*8 + i;
        #pragma unroll
        for (int jv = 0; jv < 2; jv++) {
            const int c = bx*128 + tx*8 + jv*4;
            float4 bv = *(const float4*)&bias[c];
            float v0 = acc[i][jv*4+0] + bv.x;
            float v1 = acc[i][jv*4+1] + bv.y;
            float v2 = acc[i][jv*4+2] + bv.z;
            float v3 = acc[i][jv*4+3] + bv.w;
            if (MODE == 0) {
                float4 o = {v0, v1, v2, v3};
                *(float4*)&C[(size_t)r*Dc + c] = o;
            } else if (MODE == 1) {
                const int b = r / Nc, n = r % Nc;
                const int h = c >> 6, dh = c & 63;
                float4 o = {v0*scale, v1*scale, v2*scale, v3*scale};
                *(float4*)&C[(((size_t)(b*Hc + h))*Nc + n)*DHc + dh] = o;
            } else {
                float4 o;
                o.x = 0.5f*v0*(1.f + erff(v0*0.70710678118654752f));
                o.y = 0.5f*v1*(1.f + erff(v1*0.70710678118654752f));
                o.z = 0.5f*v2*(1.f + erff(v2*0.70710678118654752f));
                o.w = 0.5f*v3*(1.f + erff(v3*0.70710678118654752f));
                *(float4*)&C[(size_t)r*Dc + c] = o;
            }
        }
    }
}

// ---------------------------------------------------------------------------
// Gate: gate[r] = sigmoid( dot(G1[r,:], Wg2) + bg2 )
// ---------------------------------------------------------------------------
__global__ void gate_k(const float* __restrict__ G1, const float* __restrict__ Wg2,
                       const float* __restrict__ bg2, float* __restrict__ gate)
{
    __shared__ float red[256];
    const int r = blockIdx.x;
    float s = 0.f;
    for (int k = threadIdx.x; k < Dc; k += 256)
        s += G1[(size_t)r*Dc + k] * Wg2[k];
    red[threadIdx.x] = s;
    __syncthreads();
    for (int o = 128; o; o >>= 1) {
        if (threadIdx.x < o) red[threadIdx.x] += red[threadIdx.x + o];
        __syncthreads();
    }
    if (threadIdx.x == 0) {
        float z = red[0] + bg2[0];
        gate[r] = 1.f / (1.f + expf(-z));
    }
}

// ---------------------------------------------------------------------------
// Attention pass A: S = Q@K^T (causal), write S to global scratch,
// online row max m and sumexp l. Block = (bh, 64-query tile), 256 thr,
// 4x4 register micro-tiles. Q is pre-scaled by DH^-0.5.
// ---------------------------------------------------------------------------
__global__ void __launch_bounds__(256)
attnA_k(const float* __restrict__ Q, const float* __restrict__ K,
        float* __restrict__ S, float* __restrict__ gm, float* __restrict__ gl)
{
    __shared__ float Qt[64][64];    // [dh][i]  (stride 64 -> float4 reads aligned)
    __shared__ float Kt[64][PAD];   // [dh][j]  (stride 68 -> float4 reads aligned)
    __shared__ float sm_m[64];
    __shared__ float sm_l[64];

    const int tid = threadIdx.x;
    const int qt = (gridDim.x - 1) - blockIdx.x;   // heavy tiles first
    const int bh = blockIdx.y;
    const int q0 = qt*64;
    const int tx = tid & 15, ty = tid >> 4;
    const int lr = tid >> 2;            // 0..63
    const int lc = (tid & 3) * 16;      // 0,16,32,48

    const float* Qb = Q + (size_t)bh*Nc*DHc;
    const float* Kb = K + (size_t)bh*Nc*DHc;

    #pragma unroll
    for (int u = 0; u < 4; u++) {
        float4 v = *(const float4*)&Qb[(size_t)(q0+lr)*DHc + lc + u*4];
        Qt[lc+u*4+0][lr] = v.x;
        Qt[lc+u*4+1][lr] = v.y;
        Qt[lc+u*4+2][lr] = v.z;
        Qt[lc+u*4+3][lr] = v.w;
    }
    if (tid < 64) { sm_m[tid] = -1e30f; sm_l[tid] = 0.f; }

    for (int kt = 0; kt <= qt; kt++) {
        const int t0 = kt*64;
        __syncthreads();
        #pragma unroll
        for (int u = 0; u < 4; u++) {
            float4 v = *(const float4*)&Kb[(size_t)(t0+lr)*DHc + lc + u*4];
            Kt[lc+u*4+0][lr] = v.x;
            Kt[lc+u*4+1][lr] = v.y;
            Kt[lc+u*4+2][lr] = v.z;
            Kt[lc+u*4+3][lr] = v.w;
        }
        __syncthreads();

        float acc[4][4];
        #pragma unroll
        for (int i = 0; i < 4; i++)
            #pragma unroll
            for (int j = 0; j < 4; j++) acc[i][j] = 0.f;

        #pragma unroll
        for (int k = 0; k < 64; k++) {
            float4 a = *(float4*)&Qt[k][ty*4];
            float4 b = *(float4*)&Kt[k][tx*4];
            float ar[4] = {a.x,a.y,a.z,a.w};
            float br[4] = {b.x,b.y,b.z,b.w};
            #pragma unroll
            for (int i = 0; i < 4; i++)
                #pragma unroll
                for (int j = 0; j < 4; j++)
                    acc[i][j] += ar[i]*br[j];
        }

        if (kt == qt) {
            #pragma unroll
            for (int i = 0; i < 4; i++)
                #pragma unroll
                for (int j = 0; j < 4; j++)
                    if (tx*4 + j > ty*4 + i) acc[i][j] = -1e30f;
        }

        // write S tile (regs -> global, coalesced float4)
        float* Srow = S + ((size_t)bh*Nc + q0 + ty*4)*Nc + t0 + tx*4;
        #pragma unroll
        for (int i = 0; i < 4; i++) {
            float4 v = {acc[i][0], acc[i][1], acc[i][2], acc[i][3]};
            *(float4*)(Srow + (size_t)i*Nc) = v;
        }

        // online (m,l) per row; a row's 16 owners are a contiguous half-warp
        #pragma unroll
        for (int i = 0; i < 4; i++) {
            float mt = fmaxf(fmaxf(acc[i][0], acc[i][1]), fmaxf(acc[i][2], acc[i][3]));
            #pragma unroll
            for (int o = 8; o; o >>= 1) mt = fmaxf(mt, __shfl_xor_sync(0xffffffffu, mt, o));
            const float mo = sm_m[ty*4+i];
            const float mn = fmaxf(mo, mt);
            float s = __expf(acc[i][0]-mn) + __expf(acc[i][1]-mn)
                    + __expf(acc[i][2]-mn) + __expf(acc[i][3]-mn);
            #pragma unroll
            for (int o = 8; o; o >>= 1) s += __shfl_xor_sync(0xffffffffu, s, o);
            if (tx == 0) {
                sm_l[ty*4+i] = sm_l[ty*4+i]*__expf(mo - mn) + s;
                sm_m[ty*4+i] = mn;
            }
        }
    }
    __syncthreads();
    if (tid < 64) {
        gm[(size_t)bh*Nc + q0 + tid] = sm_m[tid];
        gl[(size_t)bh*Nc + q0 + tid] = sm_l[tid];
    }
}

// ---------------------------------------------------------------------------
// Attention pass B: exact p = exp(s-m)/l, entropy, O = (P*gate)@V.
// ---------------------------------------------------------------------------
__global__ void __launch_bounds__(256)
attnB_k(const float* __restrict__ S, const float* __restrict__ V,
        const float* __restrict__ gm, const float* __restrict__ gl,
        const float* __restrict__ gate, float* __restrict__ O,
        float* __restrict__ ent)
{
    __shared__ float Ps[64][PAD];  // [j][i]  (stride 68 -> float4 reads aligned)
    __shared__ float Vs[64][64];   // [j][dh]
    __shared__ float sm_e[64];
    __shared__ float sm_m[64];
    __shared__ float sm_il[64];

    const int tid = threadIdx.x;
    const int qt = (gridDim.x - 1) - blockIdx.x;
    const int bh = blockIdx.y;
    const int q0 = qt*64;
    const int tx = tid & 15, ty = tid >> 4;
    const int lr = tid >> 2;
    const int lc = (tid & 3) * 16;

    if (tid < 64) {
        sm_e[tid]  = 0.f;
        sm_m[tid]  = gm[(size_t)bh*Nc + q0 + tid];
        sm_il[tid] = 1.f / gl[(size_t)bh*Nc + q0 + tid];
    }
    __syncthreads();
    const float mi  = sm_m[lr];
    const float ili = sm_il[lr];

    const float* Vb = V + (size_t)bh*Nc*DHc;

    float acc[4][4];
    #pragma unroll
    for (int i = 0; i < 4; i++)
        #pragma unroll
        for (int j = 0; j < 4; j++) acc[i][j] = 0.f;

    for (int kt = 0; kt <= qt; kt++) {
        const int t0 = kt*64;
        __syncthreads();
        #pragma unroll
        for (int u = 0; u < 4; u++) {
            float4 v = *(const float4*)&Vb[(size_t)(t0+lr)*DHc + lc + u*4];
            *(float4*)&Vs[lr][lc+u*4] = v;
        }
        const float* Srow = S + ((size_t)bh*Nc + q0 + lr)*Nc + t0 + lc;
        float epart = 0.f;
        #pragma unroll
        for (int u = 0; u < 4; u++) {
            float4 s4 = *(const float4*)(Srow + u*4);
            float p0 = __expf(s4.x - mi)*ili;
            float p1 = __expf(s4.y - mi)*ili;
            float p2 = __expf(s4.z - mi)*ili;
            float p3 = __expf(s4.w - mi)*ili;
            epart += p0*__logf(p0 + 1e-6f) + p1*__logf(p1 + 1e-6f)
                   + p2*__logf(p2 + 1e-6f) + p3*__logf(p3 + 1e-6f);
            Ps[lc+u*4+0][lr] = p0;
            Ps[lc+u*4+1][lr] = p1;
            Ps[lc+u*4+2][lr] = p2;
            Ps[lc+u*4+3][lr] = p3;
        }
        epart += __shfl_xor_sync(0xffffffffu, epart, 1);
        epart += __shfl_xor_sync(0xffffffffu, epart, 2);
        if ((tid & 3) == 0) sm_e[lr] += epart;
        __syncthreads();

        #pragma unroll
        for (int j = 0; j < 64; j++) {
            float4 a = *(float4*)&Ps[j][ty*4];
            float4 b = *(float4*)&Vs[j][tx*4];
            float ar[4] = {a.x,a.y,a.z,a.w};
            float br[4] = {b.x,b.y,b.z,b.w};
            #pragma unroll
            for (int i = 0; i < 4; i++)
                #pragma unroll
                for (int d = 0; d < 4; d++)
                    acc[i][d] += ar[i]*br[d];
        }
    }

    const int b = bh >> 4, h = bh & 15;
    #pragma unroll
    for (int i = 0; i < 4; i++) {
        const int q = q0 + ty*4 + i;
        const float g = gate[(size_t)b*Nc + q];
        float4 v = {acc[i][0]*g, acc[i][1]*g, acc[i][2]*g, acc[i][3]*g};
        *(float4*)&O[((size_t)b*Nc + q)*Dc + h*DHc + tx*4] = v;
    }
    __syncthreads();
    if (tid < 64) ent[(size_t)bh*Nc + q0 + tid] = -sm_e[tid];
}

// ---------------------------------------------------------------------------
extern "C" void kernel_launch(void* const* d_in, const int* in_sizes, int n_in,
                              void* d_out, int out_size)
{
    const float* x   = (const float*)d_in[0];
    const float* Wq  = (const float*)d_in[2];
    const float* bq  = (const float*)d_in[3];
    const float* Wk  = (const float*)d_in[4];
    const float* bk  = (const float*)d_in[5];
    const float* Wv  = (const float*)d_in[6];
    const float* bv  = (const float*)d_in[7];
    const float* Wg1 = (const float*)d_in[8];
    const float* bg1 = (const float*)d_in[9];
    const float* Wg2 = (const float*)d_in[10];
    const float* bg2 = (const float*)d_in[11];
    const float* Wo  = (const float*)d_in[12];
    const float* bo  = (const float*)d_in[13];

    float* out = (float*)d_out;                       // [B, N, D]
    float* ent = out + (size_t)Bc*Nc*Dc;              // [B, H, N]

    float *Qp, *Kp, *Vp, *G1p, *AOp, *Gp, *Sp, *mp, *lp;
    cudaGetSymbolAddress((void**)&Qp,  g_Q);
    cudaGetSymbolAddress((void**)&Kp,  g_K);
    cudaGetSymbolAddress((void**)&Vp,  g_V);
    cudaGetSymbolAddress((void**)&G1p, g_G1);
    cudaGetSymbolAddress((void**)&AOp, g_AO);
    cudaGetSymbolAddress((void**)&Gp,  g_gate);
    cudaGetSymbolAddress((void**)&Sp,  g_S);
    cudaGetSymbolAddress((void**)&mp,  g_m);
    cudaGetSymbolAddress((void**)&lp,  g_l);

    dim3 gg(Dc/128, Mc/128);   // (8, 24)
    gemm_k<1><<<gg, 256>>>(x, Wq, bq, Qp, 0.125f);    // Q pre-scaled by DH^-0.5
    gemm_k<1><<<gg, 256>>>(x, Wk, bk, Kp, 1.f);
    gemm_k<1><<<gg, 256>>>(x, Wv, bv, Vp, 1.f);
    gemm_k<2><<<gg, 256>>>(x, Wg1, bg1, G1p, 1.f);    // GELU hidden
    gate_k<<<Mc, 256>>>(G1p, Wg2, bg2, Gp);

    dim3 ga(QT, BHc);          // (24, 32)
    attnA_k<<<ga, 256>>>(Qp, Kp, Sp, mp, lp);
    attnB_k<<<ga, 256>>>(Sp, Vp, mp, lp, Gp, AOp, ent);

    gemm_k<0><<<gg, 256>>>(AOp, Wo, bo, out, 1.f);
}

// round 5
// speedup vs baseline: 2.1763x; 1.6187x over previous
#include <cuda_runtime.h>
#include <cuda_bf16.h>
#include <math.h>
#include <stdint.h>

#define Bc 2
#define Nc 1536
#define Dc 1024
#define Hc 16
#define DHc 64
#define Mc (Bc*Nc)
#define BHc (Bc*Hc)
#define QT (Nc/64)
#define PAD 68      // padded row stride (floats) for fp32 attn tiles
#define KSTR 40     // bf16 smem row stride: 80B -> ldmatrix conflict-free

// ---------------- scratch (allocation-free rule: device globals) ------------
__device__ float g_Q[BHc*Nc*DHc];
__device__ float g_K[BHc*Nc*DHc];
__device__ float g_V[BHc*Nc*DHc];
__device__ float g_G1[Mc*Dc];
__device__ float g_AO[Mc*Dc];
__device__ float g_gate[Mc];
__device__ float g_S[(size_t)BHc*Nc*Nc];   // 302 MB score scratch
__device__ float g_m[BHc*Nc];
__device__ float g_l[BHc*Nc];
__device__ __nv_bfloat16 g_xh[Mc*Dc],  g_xl[Mc*Dc];
__device__ __nv_bfloat16 g_AOh[Mc*Dc], g_AOl[Mc*Dc];
__device__ __nv_bfloat16 g_Wth[5][Dc*Dc], g_Wtl[5][Dc*Dc];  // transposed [n][k]

// ---------------- PTX helpers ----------------------------------------------
static __device__ __forceinline__ uint32_t smem_u32(const void* p) {
    uint32_t a;
    asm("{ .reg .u64 t; cvta.to.shared.u64 t, %1; cvt.u32.u64 %0, t; }"
        : "=r"(a) : "l"(p));
    return a;
}
#define LDSM4(r0, r1, r2, r3, addr) \
    asm volatile("ldmatrix.sync.aligned.m8n8.x4.shared.b16 {%0,%1,%2,%3}, [%4];" \
                 : "=r"(r0), "=r"(r1), "=r"(r2), "=r"(r3) : "r"(addr))
#define MMA16816(d, a, b0, b1) \
    asm volatile("mma.sync.aligned.m16n8k16.row.col.f32.bf16.bf16.f32 " \
                 "{%0,%1,%2,%3}, {%4,%5,%6,%7}, {%8,%9}, {%0,%1,%2,%3};" \
                 : "+f"((d)[0]), "+f"((d)[1]), "+f"((d)[2]), "+f"((d)[3]) \
                 : "r"((a)[0]), "r"((a)[1]), "r"((a)[2]), "r"((a)[3]), \
                   "r"(b0), "r"(b1))
static __device__ __forceinline__ void cp_async16(uint32_t saddr, const void* gptr) {
    asm volatile("{ .reg .u64 g; cvta.to.global.u64 g, %1; "
                 "cp.async.cg.shared.global [%0], [g], 16; }"
                 :: "r"(saddr), "l"(gptr) : "memory");
}
#define CP_COMMIT() asm volatile("cp.async.commit_group;" ::: "memory")
#define CP_WAIT(n)  asm volatile("cp.async.wait_group %0;" :: "n"(n) : "memory")

// ---------------------------------------------------------------------------
// HMMA GEMM: C[3072,1024] = A @ Wt^T (+bias), split-bf16 3-term.
// A as bf16 hi/lo [M,K] K-major; Wt as bf16 hi/lo [N,K] K-major.
// CTA: 128x128 tile; 8 warps of 64x32; K-tile 32; cp.async double buffer.
// MODE 0: plain fp32; MODE 1: QKV scatter scaled; MODE 2: exact GELU.
// ---------------------------------------------------------------------------
template<int MODE>
__global__ void __launch_bounds__(256)
tc_gemm(const __nv_bfloat16* __restrict__ Ah, const __nv_bfloat16* __restrict__ Al,
        const __nv_bfloat16* __restrict__ Bh, const __nv_bfloat16* __restrict__ Bl,
        const float* __restrict__ bias, float* __restrict__ C, float scale)
{
    extern __shared__ __nv_bfloat16 sm[];
    const int TILE_E = 128 * KSTR;            // elements per operand tile
    const int TILE_B = TILE_E * 2;            // bytes
    const int tid = threadIdx.x, wid = tid >> 5, lane = tid & 31;
    const int m0 = blockIdx.y * 128, n0 = blockIdx.x * 128;
    const int wr = wid & 1, wc = wid >> 1;    // warp row blk (64), col blk (32)
    const uint32_t sb = smem_u32(sm);

    float acc[4][4][4];
    #pragma unroll
    for (int m = 0; m < 4; m++)
        #pragma unroll
        for (int n = 0; n < 4; n++)
            #pragma unroll
            for (int v = 0; v < 4; v++) acc[m][n][v] = 0.f;

    // issue cp.async loads for one 128x32 K-tile of all 4 operands
    auto issue = [&](int kt, int stg) {
        const int k0 = kt * 32;
        const uint32_t so = sb + stg * 4 * TILE_B;
        #pragma unroll
        for (int j = 0; j < 2; j++) {
            const int cid = tid + j * 256;         // 0..511
            const int r = cid >> 2, c = cid & 3;   // row, 16B chunk
            const uint32_t soff = (uint32_t)(r * KSTR + c * 8) * 2;
            const size_t ga = (size_t)(m0 + r) * Dc + k0 + c * 8;
            const size_t gb = (size_t)(n0 + r) * Dc + k0 + c * 8;
            cp_async16(so + soff,              Ah + ga);
            cp_async16(so + TILE_B + soff,     Al + ga);
            cp_async16(so + 2 * TILE_B + soff, Bh + gb);
            cp_async16(so + 3 * TILE_B + soff, Bl + gb);
        }
    };

    issue(0, 0);
    CP_COMMIT();

    for (int kt = 0; kt < 32; kt++) {
        const int stg = kt & 1;
        if (kt + 1 < 32) { issue(kt + 1, stg ^ 1); CP_COMMIT(); CP_WAIT(1); }
        else             { CP_WAIT(0); }
        __syncthreads();

        const uint32_t so  = sb + stg * 4 * TILE_B;
        const uint32_t aAh = so,            aAl = so + TILE_B;
        const uint32_t aBh = so + 2*TILE_B, aBl = so + 3*TILE_B;

        #pragma unroll
        for (int ks = 0; ks < 2; ks++) {
            const int k0 = ks * 16;
            uint32_t bhf[8], blf[8];
            #pragma unroll
            for (int pr = 0; pr < 2; pr++) {
                const int row = wc*32 + pr*16 + ((lane >> 4) & 1)*8 + (lane & 7);
                const int col = k0 + ((lane >> 3) & 1)*8;
                const uint32_t off = (uint32_t)(row * KSTR + col) * 2;
                LDSM4(bhf[pr*4+0], bhf[pr*4+1], bhf[pr*4+2], bhf[pr*4+3], aBh + off);
                LDSM4(blf[pr*4+0], blf[pr*4+1], blf[pr*4+2], blf[pr*4+3], aBl + off);
            }
            #pragma unroll
            for (int m = 0; m < 4; m++) {
                const int row = wr*64 + m*16 + (lane & 7) + ((lane >> 3) & 1)*8;
                const int col = k0 + (lane >> 4)*8;
                const uint32_t off = (uint32_t)(row * KSTR + col) * 2;
                uint32_t ah[4], al[4];
                LDSM4(ah[0], ah[1], ah[2], ah[3], aAh + off);
                LDSM4(al[0], al[1], al[2], al[3], aAl + off);
                #pragma unroll
                for (int n = 0; n < 4; n++) {
                    MMA16816(acc[m][n], ah, bhf[n*2], bhf[n*2+1]);
                    MMA16816(acc[m][n], ah, blf[n*2], blf[n*2+1]);
                    MMA16816(acc[m][n], al, bhf[n*2], bhf[n*2+1]);
                }
            }
        }
        __syncthreads();
    }

    // epilogue: registers -> global, float2 per (row-half, n-tile)
    #pragma unroll
    for (int m = 0; m < 4; m++) {
        #pragma unroll
        for (int n = 0; n < 4; n++) {
            const int c = n0 + wc*32 + n*8 + (lane & 3)*2;
            const float b0 = bias[c], b1 = bias[c + 1];
            #pragma unroll
            for (int hv = 0; hv < 2; hv++) {
                const int r = m0 + wr*64 + m*16 + (lane >> 2) + hv*8;
                float v0 = acc[m][n][hv*2+0] + b0;
                float v1 = acc[m][n][hv*2+1] + b1;
                if (MODE == 0) {
                    float2 o = {v0, v1};
                    *(float2*)&C[(size_t)r*Dc + c] = o;
                } else if (MODE == 1) {
                    const int bb = r / Nc, nn = r % Nc;
                    const int h = c >> 6, dh = c & 63;
                    float2 o = {v0*scale, v1*scale};
                    *(float2*)&C[(((size_t)(bb*Hc + h))*Nc + nn)*DHc + dh] = o;
                } else {
                    float2 o;
                    o.x = 0.5f*v0*(1.f + erff(v0*0.70710678118654752f));
                    o.y = 0.5f*v1*(1.f + erff(v1*0.70710678118654752f));
                    *(float2*)&C[(size_t)r*Dc + c] = o;
                }
            }
        }
    }
}

// ---------------------------------------------------------------------------
// fp32 -> bf16 hi/lo split (element-wise, float4 vectorized)
// ---------------------------------------------------------------------------
__global__ void split_k(const float* __restrict__ in, __nv_bfloat16* __restrict__ hi,
                        __nv_bfloat16* __restrict__ lo, int n4)
{
    const int i = blockIdx.x * 256 + threadIdx.x;
    if (i >= n4) return;
    float4 v = ((const float4*)in)[i];
    __nv_bfloat16 h0 = __float2bfloat16(v.x);
    __nv_bfloat16 h1 = __float2bfloat16(v.y);
    __nv_bfloat16 h2 = __float2bfloat16(v.z);
    __nv_bfloat16 h3 = __float2bfloat16(v.w);
    __nv_bfloat162 H0; H0.x = h0; H0.y = h1;
    __nv_bfloat162 H1; H1.x = h2; H1.y = h3;
    __nv_bfloat162 L0, L1;
    L0.x = __float2bfloat16(v.x - __bfloat162float(h0));
    L0.y = __float2bfloat16(v.y - __bfloat162float(h1));
    L1.x = __float2bfloat16(v.z - __bfloat162float(h2));
    L1.y = __float2bfloat16(v.w - __bfloat162float(h3));
    ((__nv_bfloat162*)hi)[i * 2 + 0] = H0;
    ((__nv_bfloat162*)hi)[i * 2 + 1] = H1;
    ((__nv_bfloat162*)lo)[i * 2 + 0] = L0;
    ((__nv_bfloat162*)lo)[i * 2 + 1] = L1;
}

// ---------------------------------------------------------------------------
// Weight transpose + split: W[k][n] fp32 -> out[n][k] bf16 hi/lo
// ---------------------------------------------------------------------------
__global__ void tsplit_k(const float* __restrict__ W, __nv_bfloat16* __restrict__ th,
                         __nv_bfloat16* __restrict__ tl)
{
    __shared__ float t[32][33];
    const int k0 = blockIdx.y * 32, n0 = blockIdx.x * 32;
    const int lane = threadIdx.x & 31, wr = threadIdx.x >> 5;
    #pragma unroll
    for (int i = 0; i < 4; i++)
        t[wr + i * 8][lane] = W[(size_t)(k0 + wr + i * 8) * Dc + n0 + lane];
    __syncthreads();
    #pragma unroll
    for (int i = 0; i < 4; i++) {
        float v = t[lane][wr + i * 8];
        __nv_bfloat16 h = __float2bfloat16(v);
        th[(size_t)(n0 + wr + i * 8) * Dc + k0 + lane] = h;
        tl[(size_t)(n0 + wr + i * 8) * Dc + k0 + lane] =
            __float2bfloat16(v - __bfloat162float(h));
    }
}

// ---------------------------------------------------------------------------
// Gate: gate[r] = sigmoid( dot(G1[r,:], Wg2) + bg2 )
// ---------------------------------------------------------------------------
__global__ void gate_k(const float* __restrict__ G1, const float* __restrict__ Wg2,
                       const float* __restrict__ bg2, float* __restrict__ gate)
{
    __shared__ float red[256];
    const int r = blockIdx.x;
    float s = 0.f;
    for (int k = threadIdx.x; k < Dc; k += 256)
        s += G1[(size_t)r*Dc + k] * Wg2[k];
    red[threadIdx.x] = s;
    __syncthreads();
    for (int o = 128; o; o >>= 1) {
        if (threadIdx.x < o) red[threadIdx.x] += red[threadIdx.x + o];
        __syncthreads();
    }
    if (threadIdx.x == 0) {
        float z = red[0] + bg2[0];
        gate[r] = 1.f / (1.f + expf(-z));
    }
}

// ---------------------------------------------------------------------------
// Attention pass A: S = Q@K^T (causal) -> global scratch + online (m,l).
// ---------------------------------------------------------------------------
__global__ void __launch_bounds__(256)
attnA_k(const float* __restrict__ Q, const float* __restrict__ K,
        float* __restrict__ S, float* __restrict__ gm, float* __restrict__ gl)
{
    __shared__ float Qt[64][64];
    __shared__ float Kt[64][PAD];
    __shared__ float sm_m[64];
    __shared__ float sm_l[64];

    const int tid = threadIdx.x;
    const int qt = (gridDim.x - 1) - blockIdx.x;
    const int bh = blockIdx.y;
    const int q0 = qt*64;
    const int tx = tid & 15, ty = tid >> 4;
    const int lr = tid >> 2;
    const int lc = (tid & 3) * 16;

    const float* Qb = Q + (size_t)bh*Nc*DHc;
    const float* Kb = K + (size_t)bh*Nc*DHc;

    #pragma unroll
    for (int u = 0; u < 4; u++) {
        float4 v = *(const float4*)&Qb[(size_t)(q0+lr)*DHc + lc + u*4];
        Qt[lc+u*4+0][lr] = v.x;
        Qt[lc+u*4+1][lr] = v.y;
        Qt[lc+u*4+2][lr] = v.z;
        Qt[lc+u*4+3][lr] = v.w;
    }
    if (tid < 64) { sm_m[tid] = -1e30f; sm_l[tid] = 0.f; }

    for (int kt = 0; kt <= qt; kt++) {
        const int t0 = kt*64;
        __syncthreads();
        #pragma unroll
        for (int u = 0; u < 4; u++) {
            float4 v = *(const float4*)&Kb[(size_t)(t0+lr)*DHc + lc + u*4];
            Kt[lc+u*4+0][lr] = v.x;
            Kt[lc+u*4+1][lr] = v.y;
            Kt[lc+u*4+2][lr] = v.z;
            Kt[lc+u*4+3][lr] = v.w;
        }
        __syncthreads();

        float acc[4][4];
        #pragma unroll
        for (int i = 0; i < 4; i++)
            #pragma unroll
            for (int j = 0; j < 4; j++) acc[i][j] = 0.f;

        #pragma unroll
        for (int k = 0; k < 64; k++) {
            float4 a = *(float4*)&Qt[k][ty*4];
            float4 b = *(float4*)&Kt[k][tx*4];
            float ar[4] = {a.x,a.y,a.z,a.w};
            float br[4] = {b.x,b.y,b.z,b.w};
            #pragma unroll
            for (int i = 0; i < 4; i++)
                #pragma unroll
                for (int j = 0; j < 4; j++)
                    acc[i][j] += ar[i]*br[j];
        }

        if (kt == qt) {
            #pragma unroll
            for (int i = 0; i < 4; i++)
                #pragma unroll
                for (int j = 0; j < 4; j++)
                    if (tx*4 + j > ty*4 + i) acc[i][j] = -1e30f;
        }

        float* Srow = S + ((size_t)bh*Nc + q0 + ty*4)*Nc + t0 + tx*4;
        #pragma unroll
        for (int i = 0; i < 4; i++) {
            float4 v = {acc[i][0], acc[i][1], acc[i][2], acc[i][3]};
            *(float4*)(Srow + (size_t)i*Nc) = v;
        }

        #pragma unroll
        for (int i = 0; i < 4; i++) {
            float mt = fmaxf(fmaxf(acc[i][0], acc[i][1]), fmaxf(acc[i][2], acc[i][3]));
            #pragma unroll
            for (int o = 8; o; o >>= 1) mt = fmaxf(mt, __shfl_xor_sync(0xffffffffu, mt, o));
            const float mo = sm_m[ty*4+i];
            const float mn = fmaxf(mo, mt);
            float s = __expf(acc[i][0]-mn) + __expf(acc[i][1]-mn)
                    + __expf(acc[i][2]-mn) + __expf(acc[i][3]-mn);
            #pragma unroll
            for (int o = 8; o; o >>= 1) s += __shfl_xor_sync(0xffffffffu, s, o);
            if (tx == 0) {
                sm_l[ty*4+i] = sm_l[ty*4+i]*__expf(mo - mn) + s;
                sm_m[ty*4+i] = mn;
            }
        }
    }
    __syncthreads();
    if (tid < 64) {
        gm[(size_t)bh*Nc + q0 + tid] = sm_m[tid];
        gl[(size_t)bh*Nc + q0 + tid] = sm_l[tid];
    }
}

// ---------------------------------------------------------------------------
// Attention pass B: exact p = exp(s-m)/l, entropy, O = (P*gate)@V.
// ---------------------------------------------------------------------------
__global__ void __launch_bounds__(256)
attnB_k(const float* __restrict__ S, const float* __restrict__ V,
        const float* __restrict__ gm, const float* __restrict__ gl,
        const float* __restrict__ gate, float* __restrict__ O,
        float* __restrict__ ent)
{
    __shared__ float Ps[64][PAD];
    __shared__ float Vs[64][64];
    __shared__ float sm_e[64];
    __shared__ float sm_m[64];
    __shared__ float sm_il[64];

    const int tid = threadIdx.x;
    const int qt = (gridDim.x - 1) - blockIdx.x;
    const int bh = blockIdx.y;
    const int q0 = qt*64;
    const int tx = tid & 15, ty = tid >> 4;
    const int lr = tid >> 2;
    const int lc = (tid & 3) * 16;

    if (tid < 64) {
        sm_e[tid]  = 0.f;
        sm_m[tid]  = gm[(size_t)bh*Nc + q0 + tid];
        sm_il[tid] = 1.f / gl[(size_t)bh*Nc + q0 + tid];
    }
    __syncthreads();
    const float mi  = sm_m[lr];
    const float ili = sm_il[lr];

    const float* Vb = V + (size_t)bh*Nc*DHc;

    float acc[4][4];
    #pragma unroll
    for (int i = 0; i < 4; i++)
        #pragma unroll
        for (int j = 0; j < 4; j++) acc[i][j] = 0.f;

    for (int kt = 0; kt <= qt; kt++) {
        const int t0 = kt*64;
        __syncthreads();
        #pragma unroll
        for (int u = 0; u < 4; u++) {
            float4 v = *(const float4*)&Vb[(size_t)(t0+lr)*DHc + lc + u*4];
            *(float4*)&Vs[lr][lc+u*4] = v;
        }
        const float* Srow = S + ((size_t)bh*Nc + q0 + lr)*Nc + t0 + lc;
        float epart = 0.f;
        #pragma unroll
        for (int u = 0; u < 4; u++) {
            float4 s4 = *(const float4*)(Srow + u*4);
            float p0 = __expf(s4.x - mi)*ili;
            float p1 = __expf(s4.y - mi)*ili;
            float p2 = __expf(s4.z - mi)*ili;
            float p3 = __expf(s4.w - mi)*ili;
            epart += p0*__logf(p0 + 1e-6f) + p1*__logf(p1 + 1e-6f)
                   + p2*__logf(p2 + 1e-6f) + p3*__logf(p3 + 1e-6f);
            Ps[lc+u*4+0][lr] = p0;
            Ps[lc+u*4+1][lr] = p1;
            Ps[lc+u*4+2][lr] = p2;
            Ps[lc+u*4+3][lr] = p3;
        }
        epart += __shfl_xor_sync(0xffffffffu, epart, 1);
        epart += __shfl_xor_sync(0xffffffffu, epart, 2);
        if ((tid & 3) == 0) sm_e[lr] += epart;
        __syncthreads();

        #pragma unroll
        for (int j = 0; j < 64; j++) {
            float4 a = *(float4*)&Ps[j][ty*4];
            float4 b = *(float4*)&Vs[j][tx*4];
            float ar[4] = {a.x,a.y,a.z,a.w};
            float br[4] = {b.x,b.y,b.z,b.w};
            #pragma unroll
            for (int i = 0; i < 4; i++)
                #pragma unroll
                for (int d = 0; d < 4; d++)
                    acc[i][d] += ar[i]*br[d];
        }
    }

    const int b = bh >> 4, h = bh & 15;
    #pragma unroll
    for (int i = 0; i < 4; i++) {
        const int q = q0 + ty*4 + i;
        const float g = gate[(size_t)b*Nc + q];
        float4 v = {acc[i][0]*g, acc[i][1]*g, acc[i][2]*g, acc[i][3]*g};
        *(float4*)&O[((size_t)b*Nc + q)*Dc + h*DHc + tx*4] = v;
    }
    __syncthreads();
    if (tid < 64) ent[(size_t)bh*Nc + q0 + tid] = -sm_e[tid];
}

// ---------------------------------------------------------------------------
extern "C" void kernel_launch(void* const* d_in, const int* in_sizes, int n_in,
                              void* d_out, int out_size)
{
    const float* x   = (const float*)d_in[0];
    const float* Wq  = (const float*)d_in[2];
    const float* bq  = (const float*)d_in[3];
    const float* Wk  = (const float*)d_in[4];
    const float* bk  = (const float*)d_in[5];
    const float* Wv  = (const float*)d_in[6];
    const float* bv  = (const float*)d_in[7];
    const float* Wg1 = (const float*)d_in[8];
    const float* bg1 = (const float*)d_in[9];
    const float* Wg2 = (const float*)d_in[10];
    const float* bg2 = (const float*)d_in[11];
    const float* Wo  = (const float*)d_in[12];
    const float* bo  = (const float*)d_in[13];

    float* out = (float*)d_out;                       // [B, N, D]
    float* ent = out + (size_t)Bc*Nc*Dc;              // [B, H, N]

    float *Qp, *Kp, *Vp, *G1p, *AOp, *Gp, *Sp, *mp, *lp;
    __nv_bfloat16 *xh, *xl, *AOh, *AOl, *Wth, *Wtl;
    cudaGetSymbolAddress((void**)&Qp,  g_Q);
    cudaGetSymbolAddress((void**)&Kp,  g_K);
    cudaGetSymbolAddress((void**)&Vp,  g_V);
    cudaGetSymbolAddress((void**)&G1p, g_G1);
    cudaGetSymbolAddress((void**)&AOp, g_AO);
    cudaGetSymbolAddress((void**)&Gp,  g_gate);
    cudaGetSymbolAddress((void**)&Sp,  g_S);
    cudaGetSymbolAddress((void**)&mp,  g_m);
    cudaGetSymbolAddress((void**)&lp,  g_l);
    cudaGetSymbolAddress((void**)&xh,  g_xh);
    cudaGetSymbolAddress((void**)&xl,  g_xl);
    cudaGetSymbolAddress((void**)&AOh, g_AOh);
    cudaGetSymbolAddress((void**)&AOl, g_AOl);
    cudaGetSymbolAddress((void**)&Wth, g_Wth);
    cudaGetSymbolAddress((void**)&Wtl, g_Wtl);

    // smem: 2 stages * 4 operands * 128*40 bf16 = 81920 B
    const int TCSMEM = 2 * 4 * 128 * KSTR * 2;
    cudaFuncSetAttribute(tc_gemm<0>, cudaFuncAttributeMaxDynamicSharedMemorySize, TCSMEM);
    cudaFuncSetAttribute(tc_gemm<1>, cudaFuncAttributeMaxDynamicSharedMemorySize, TCSMEM);
    cudaFuncSetAttribute(tc_gemm<2>, cudaFuncAttributeMaxDynamicSharedMemorySize, TCSMEM);

    // split activations + weights (transposed)
    split_k<<<Mc*Dc/4/256, 256>>>(x, xh, xl, Mc*Dc/4);
    dim3 gt(32, 32);
    tsplit_k<<<gt, 256>>>(Wq,  Wth + 0*(size_t)Dc*Dc, Wtl + 0*(size_t)Dc*Dc);
    tsplit_k<<<gt, 256>>>(Wk,  Wth + 1*(size_t)Dc*Dc, Wtl + 1*(size_t)Dc*Dc);
    tsplit_k<<<gt, 256>>>(Wv,  Wth + 2*(size_t)Dc*Dc, Wtl + 2*(size_t)Dc*Dc);
    tsplit_k<<<gt, 256>>>(Wg1, Wth + 3*(size_t)Dc*Dc, Wtl + 3*(size_t)Dc*Dc);
    tsplit_k<<<gt, 256>>>(Wo,  Wth + 4*(size_t)Dc*Dc, Wtl + 4*(size_t)Dc*Dc);

    dim3 gg(Dc/128, Mc/128);   // (8, 24)
    tc_gemm<1><<<gg, 256, TCSMEM>>>(xh, xl, Wth + 0*(size_t)Dc*Dc, Wtl + 0*(size_t)Dc*Dc, bq,  Qp,  0.125f);
    tc_gemm<1><<<gg, 256, TCSMEM>>>(xh, xl, Wth + 1*(size_t)Dc*Dc, Wtl + 1*(size_t)Dc*Dc, bk,  Kp,  1.f);
    tc_gemm<1><<<gg, 256, TCSMEM>>>(xh, xl, Wth + 2*(size_t)Dc*Dc, Wtl + 2*(size_t)Dc*Dc, bv,  Vp,  1.f);
    tc_gemm<2><<<gg, 256, TCSMEM>>>(xh, xl, Wth + 3*(size_t)Dc*Dc, Wtl + 3*(size_t)Dc*Dc, bg1, G1p, 1.f);
    gate_k<<<Mc, 256>>>(G1p, Wg2, bg2, Gp);

    dim3 ga(QT, BHc);          // (24, 32)
    attnA_k<<<ga, 256>>>(Qp, Kp, Sp, mp, lp);
    attnB_k<<<ga, 256>>>(Sp, Vp, mp, lp, Gp, AOp, ent);

    split_k<<<Mc*Dc/4/256, 256>>>(AOp, AOh, AOl, Mc*Dc/4);
    tc_gemm<0><<<gg, 256, TCSMEM>>>(AOh, AOl, Wth + 4*(size_t)Dc*Dc, Wtl + 4*(size_t)Dc*Dc, bo, out, 1.f);
}

// round 6
// speedup vs baseline: 3.0318x; 1.3931x over previous
#include <cuda_runtime.h>
#include <cuda_bf16.h>
#include <math.h>
#include <stdint.h>

#define Bc 2
#define Nc 1536
#define Dc 1024
#define Hc 16
#define DHc 64
#define Mc (Bc*Nc)
#define BHc (Bc*Hc)
#define KSTR 40     // gemm bf16 smem row stride (80B -> ldmatrix conflict-free)

// attention smem geometry (bf16 element offsets)
#define QS 72       // 64-wide tiles padded: 144B = 9*16B
#define PS 136      // 128-wide tiles padded: 272B = 17*16B
#define OQ_H 0
#define OQ_L 9216
#define OK_H 18432
#define OK_L 27648
#define OV_H 36864
#define OV_L 45568
#define OP_H 54272
#define OP_L 71680
#define ATT_SMEM_B (89088*2)

// ---------------- scratch (allocation-free rule: device globals) ------------
__device__ float g_V[BHc*Nc*DHc];
__device__ float g_G1[Mc*Dc];
__device__ float g_gate[Mc];
__device__ __nv_bfloat16 g_xh[Mc*Dc],  g_xl[Mc*Dc];
__device__ __nv_bfloat16 g_qh[BHc*Nc*DHc], g_ql[BHc*Nc*DHc];
__device__ __nv_bfloat16 g_kh[BHc*Nc*DHc], g_kl[BHc*Nc*DHc];
__device__ __nv_bfloat16 g_vth[BHc*DHc*Nc], g_vtl[BHc*DHc*Nc];  // [bh][dh][n]
__device__ __nv_bfloat16 g_AOh[Mc*Dc], g_AOl[Mc*Dc];
__device__ __nv_bfloat16 g_Wth[5][Dc*Dc], g_Wtl[5][Dc*Dc];      // [n][k]

// ---------------- PTX helpers ----------------------------------------------
static __device__ __forceinline__ uint32_t smem_u32(const void* p) {
    uint32_t a;
    asm("{ .reg .u64 t; cvta.to.shared.u64 t, %1; cvt.u32.u64 %0, t; }"
        : "=r"(a) : "l"(p));
    return a;
}
#define LDSM4(r0, r1, r2, r3, addr) \
    asm volatile("ldmatrix.sync.aligned.m8n8.x4.shared.b16 {%0,%1,%2,%3}, [%4];" \
                 : "=r"(r0), "=r"(r1), "=r"(r2), "=r"(r3) : "r"(addr))
#define MMA16816(d, a, b0, b1) \
    asm volatile("mma.sync.aligned.m16n8k16.row.col.f32.bf16.bf16.f32 " \
                 "{%0,%1,%2,%3}, {%4,%5,%6,%7}, {%8,%9}, {%0,%1,%2,%3};" \
                 : "+f"((d)[0]), "+f"((d)[1]), "+f"((d)[2]), "+f"((d)[3]) \
                 : "r"((a)[0]), "r"((a)[1]), "r"((a)[2]), "r"((a)[3]), \
                   "r"(b0), "r"(b1))
static __device__ __forceinline__ void cp_async16(uint32_t saddr, const void* gptr) {
    asm volatile("{ .reg .u64 g; cvta.to.global.u64 g, %1; "
                 "cp.async.cg.shared.global [%0], [g], 16; }"
                 :: "r"(saddr), "l"(gptr) : "memory");
}
#define CP_COMMIT() asm volatile("cp.async.commit_group;" ::: "memory")
#define CP_WAIT(n)  asm volatile("cp.async.wait_group %0;" :: "n"(n) : "memory")

static __device__ __forceinline__ __nv_bfloat162 split2(float a, float b,
                                                        __nv_bfloat162& lo) {
    __nv_bfloat16 ha = __float2bfloat16(a), hb = __float2bfloat16(b);
    lo.x = __float2bfloat16(a - __bfloat162float(ha));
    lo.y = __float2bfloat16(b - __bfloat162float(hb));
    __nv_bfloat162 hi; hi.x = ha; hi.y = hb;
    return hi;
}

// ---------------------------------------------------------------------------
// HMMA GEMM: C[3072,1024] = A @ Wt^T (+bias), split-bf16 3-term.
// MODE 0: fp32 out; MODE 1: fp32 QKV scatter scaled; MODE 2: exact GELU fp32;
// MODE 3: split-bf16 QKV scatter scaled (Ch/Cl outputs).
// ---------------------------------------------------------------------------
template<int MODE>
__global__ void __launch_bounds__(256)
tc_gemm(const __nv_bfloat16* __restrict__ Ah, const __nv_bfloat16* __restrict__ Al,
        const __nv_bfloat16* __restrict__ Bh, const __nv_bfloat16* __restrict__ Bl,
        const float* __restrict__ bias, float* __restrict__ C,
        __nv_bfloat16* __restrict__ Ch, __nv_bfloat16* __restrict__ Cl, float scale)
{
    extern __shared__ __nv_bfloat16 sm[];
    const int TILE_E = 128 * KSTR;
    const int TILE_B = TILE_E * 2;
    const int tid = threadIdx.x, wid = tid >> 5, lane = tid & 31;
    const int m0 = blockIdx.y * 128, n0 = blockIdx.x * 128;
    const int wr = wid & 1, wc = wid >> 1;
    const uint32_t sb = smem_u32(sm);

    float acc[4][4][4];
    #pragma unroll
    for (int m = 0; m < 4; m++)
        #pragma unroll
        for (int n = 0; n < 4; n++)
            #pragma unroll
            for (int v = 0; v < 4; v++) acc[m][n][v] = 0.f;

    auto issue = [&](int kt, int stg) {
        const int k0 = kt * 32;
        const uint32_t so = sb + stg * 4 * TILE_B;
        #pragma unroll
        for (int j = 0; j < 2; j++) {
            const int cid = tid + j * 256;
            const int r = cid >> 2, c = cid & 3;
            const uint32_t soff = (uint32_t)(r * KSTR + c * 8) * 2;
            const size_t ga = (size_t)(m0 + r) * Dc + k0 + c * 8;
            const size_t gb = (size_t)(n0 + r) * Dc + k0 + c * 8;
            cp_async16(so + soff,              Ah + ga);
            cp_async16(so + TILE_B + soff,     Al + ga);
            cp_async16(so + 2 * TILE_B + soff, Bh + gb);
            cp_async16(so + 3 * TILE_B + soff, Bl + gb);
        }
    };

    issue(0, 0);
    CP_COMMIT();

    for (int kt = 0; kt < 32; kt++) {
        const int stg = kt & 1;
        if (kt + 1 < 32) { issue(kt + 1, stg ^ 1); CP_COMMIT(); CP_WAIT(1); }
        else             { CP_WAIT(0); }
        __syncthreads();

        const uint32_t so  = sb + stg * 4 * TILE_B;
        const uint32_t aAh = so,            aAl = so + TILE_B;
        const uint32_t aBh = so + 2*TILE_B, aBl = so + 3*TILE_B;

        #pragma unroll
        for (int ks = 0; ks < 2; ks++) {
            const int k0 = ks * 16;
            uint32_t bhf[8], blf[8];
            #pragma unroll
            for (int pr = 0; pr < 2; pr++) {
                const int row = wc*32 + pr*16 + ((lane >> 4) & 1)*8 + (lane & 7);
                const int col = k0 + ((lane >> 3) & 1)*8;
                const uint32_t off = (uint32_t)(row * KSTR + col) * 2;
                LDSM4(bhf[pr*4+0], bhf[pr*4+1], bhf[pr*4+2], bhf[pr*4+3], aBh + off);
                LDSM4(blf[pr*4+0], blf[pr*4+1], blf[pr*4+2], blf[pr*4+3], aBl + off);
            }
            #pragma unroll
            for (int m = 0; m < 4; m++) {
                const int row = wr*64 + m*16 + (lane & 7) + ((lane >> 3) & 1)*8;
                const int col = k0 + (lane >> 4)*8;
                const uint32_t off = (uint32_t)(row * KSTR + col) * 2;
                uint32_t ah[4], al[4];
                LDSM4(ah[0], ah[1], ah[2], ah[3], aAh + off);
                LDSM4(al[0], al[1], al[2], al[3], aAl + off);
                #pragma unroll
                for (int n = 0; n < 4; n++) {
                    MMA16816(acc[m][n], ah, bhf[n*2], bhf[n*2+1]);
                    MMA16816(acc[m][n], ah, blf[n*2], blf[n*2+1]);
                    MMA16816(acc[m][n], al, bhf[n*2], bhf[n*2+1]);
                }
            }
        }
        __syncthreads();
    }

    #pragma unroll
    for (int m = 0; m < 4; m++) {
        #pragma unroll
        for (int n = 0; n < 4; n++) {
            const int c = n0 + wc*32 + n*8 + (lane & 3)*2;
            const float b0 = bias[c], b1 = bias[c + 1];
            #pragma unroll
            for (int hv = 0; hv < 2; hv++) {
                const int r = m0 + wr*64 + m*16 + (lane >> 2) + hv*8;
                float v0 = acc[m][n][hv*2+0] + b0;
                float v1 = acc[m][n][hv*2+1] + b1;
                if (MODE == 0) {
                    float2 o = {v0, v1};
                    *(float2*)&C[(size_t)r*Dc + c] = o;
                } else if (MODE == 1) {
                    const int bb = r / Nc, nn = r % Nc;
                    const int h = c >> 6, dh = c & 63;
                    float2 o = {v0*scale, v1*scale};
                    *(float2*)&C[(((size_t)(bb*Hc + h))*Nc + nn)*DHc + dh] = o;
                } else if (MODE == 2) {
                    float2 o;
                    o.x = 0.5f*v0*(1.f + erff(v0*0.70710678118654752f));
                    o.y = 0.5f*v1*(1.f + erff(v1*0.70710678118654752f));
                    *(float2*)&C[(size_t)r*Dc + c] = o;
                } else {
                    const int bb = r / Nc, nn = r % Nc;
                    const int h = c >> 6, dh = c & 63;
                    const size_t ad = (((size_t)(bb*Hc + h))*Nc + nn)*DHc + dh;
                    __nv_bfloat162 lo;
                    __nv_bfloat162 hi = split2(v0*scale, v1*scale, lo);
                    *(__nv_bfloat162*)&Ch[ad] = hi;
                    *(__nv_bfloat162*)&Cl[ad] = lo;
                }
            }
        }
    }
}

// ---------------------------------------------------------------------------
// fp32 -> bf16 hi/lo split
// ---------------------------------------------------------------------------
__global__ void split_k(const float* __restrict__ in, __nv_bfloat16* __restrict__ hi,
                        __nv_bfloat16* __restrict__ lo, int n4)
{
    const int i = blockIdx.x * 256 + threadIdx.x;
    if (i >= n4) return;
    float4 v = ((const float4*)in)[i];
    __nv_bfloat162 L0, L1;
    __nv_bfloat162 H0 = split2(v.x, v.y, L0);
    __nv_bfloat162 H1 = split2(v.z, v.w, L1);
    ((__nv_bfloat162*)hi)[i * 2 + 0] = H0;
    ((__nv_bfloat162*)hi)[i * 2 + 1] = H1;
    ((__nv_bfloat162*)lo)[i * 2 + 0] = L0;
    ((__nv_bfloat162*)lo)[i * 2 + 1] = L1;
}

// ---------------------------------------------------------------------------
// Weight transpose + split: W[k][n] fp32 -> out[n][k] bf16 hi/lo
// ---------------------------------------------------------------------------
__global__ void tsplit_k(const float* __restrict__ W, __nv_bfloat16* __restrict__ th,
                         __nv_bfloat16* __restrict__ tl)
{
    __shared__ float t[32][33];
    const int k0 = blockIdx.y * 32, n0 = blockIdx.x * 32;
    const int lane = threadIdx.x & 31, wr = threadIdx.x >> 5;
    #pragma unroll
    for (int i = 0; i < 4; i++)
        t[wr + i * 8][lane] = W[(size_t)(k0 + wr + i * 8) * Dc + n0 + lane];
    __syncthreads();
    #pragma unroll
    for (int i = 0; i < 4; i++) {
        float v = t[lane][wr + i * 8];
        __nv_bfloat16 h = __float2bfloat16(v);
        th[(size_t)(n0 + wr + i * 8) * Dc + k0 + lane] = h;
        tl[(size_t)(n0 + wr + i * 8) * Dc + k0 + lane] =
            __float2bfloat16(v - __bfloat162float(h));
    }
}

// ---------------------------------------------------------------------------
// V transpose + split: V[bh][n][dh] fp32 -> Vt[bh][dh][n] bf16 hi/lo
// ---------------------------------------------------------------------------
__global__ void vt_k(const float* __restrict__ V, __nv_bfloat16* __restrict__ th,
                     __nv_bfloat16* __restrict__ tl)
{
    __shared__ float t[32][33];
    const int bh = blockIdx.z;
    const int n0 = blockIdx.x * 32, d0 = blockIdx.y * 32;
    const int lane = threadIdx.x & 31, wr = threadIdx.x >> 5;
    #pragma unroll
    for (int i = 0; i < 4; i++)
        t[wr + i * 8][lane] = V[((size_t)bh*Nc + n0 + wr + i*8)*DHc + d0 + lane];
    __syncthreads();
    #pragma unroll
    for (int i = 0; i < 4; i++) {
        float v = t[lane][wr + i * 8];
        __nv_bfloat16 h = __float2bfloat16(v);
        const size_t ad = ((size_t)bh*DHc + d0 + wr + i*8)*Nc + n0 + lane;
        th[ad] = h;
        tl[ad] = __float2bfloat16(v - __bfloat162float(h));
    }
}

// ---------------------------------------------------------------------------
// Gate: gate[r] = sigmoid( dot(G1[r,:], Wg2) + bg2 )
// ---------------------------------------------------------------------------
__global__ void gate_k(const float* __restrict__ G1, const float* __restrict__ Wg2,
                       const float* __restrict__ bg2, float* __restrict__ gate)
{
    __shared__ float red[256];
    const int r = blockIdx.x;
    float s = 0.f;
    for (int k = threadIdx.x; k < Dc; k += 256)
        s += G1[(size_t)r*Dc + k] * Wg2[k];
    red[threadIdx.x] = s;
    __syncthreads();
    for (int o = 128; o; o >>= 1) {
        if (threadIdx.x < o) red[threadIdx.x] += red[threadIdx.x + o];
        __syncthreads();
    }
    if (threadIdx.x == 0) {
        float z = red[0] + bg2[0];
        gate[r] = 1.f / (1.f + expf(-z));
    }
}

// ---------------------------------------------------------------------------
// Fused causal attention (HMMA split-bf16, recompute-S):
// CTA = (bh, 128-query tile); 8 warps x 16 query rows.
// Phase 1: online (m,l) over S = Q@K^T.  Phase 2: recompute S, exact p,
// entropy, P@V with V^T tiles; outputs AO as split bf16 + entropy.
// ---------------------------------------------------------------------------
__device__ __forceinline__ void attn_S(uint32_t sb, int w, int lane, float sacc[16][4])
{
    #pragma unroll
    for (int nt = 0; nt < 16; nt++)
        #pragma unroll
        for (int v = 0; v < 4; v++) sacc[nt][v] = 0.f;
    #pragma unroll
    for (int ks = 0; ks < 4; ks++) {
        const int ar = 16*w + (lane & 7) + ((lane >> 3) & 1)*8;
        const int ac = ks*16 + (lane >> 4)*8;
        uint32_t ah[4], al[4];
        LDSM4(ah[0], ah[1], ah[2], ah[3], sb + (uint32_t)(OQ_H + ar*QS + ac)*2);
        LDSM4(al[0], al[1], al[2], al[3], sb + (uint32_t)(OQ_L + ar*QS + ac)*2);
        #pragma unroll
        for (int np = 0; np < 8; np++) {
            const int br = np*16 + ((lane >> 4) & 1)*8 + (lane & 7);
            const int bc = ks*16 + ((lane >> 3) & 1)*8;
            uint32_t bh4[4], bl4[4];
            LDSM4(bh4[0], bh4[1], bh4[2], bh4[3], sb + (uint32_t)(OK_H + br*QS + bc)*2);
            LDSM4(bl4[0], bl4[1], bl4[2], bl4[3], sb + (uint32_t)(OK_L + br*QS + bc)*2);
            MMA16816(sacc[2*np],   ah, bh4[0], bh4[1]);
            MMA16816(sacc[2*np],   ah, bl4[0], bl4[1]);
            MMA16816(sacc[2*np],   al, bh4[0], bh4[1]);
            MMA16816(sacc[2*np+1], ah, bh4[2], bh4[3]);
            MMA16816(sacc[2*np+1], ah, bl4[2], bl4[3]);
            MMA16816(sacc[2*np+1], al, bh4[2], bh4[3]);
        }
    }
}

__global__ void __launch_bounds__(256)
attn_k(const __nv_bfloat16* __restrict__ Qh, const __nv_bfloat16* __restrict__ Ql,
       const __nv_bfloat16* __restrict__ Kh, const __nv_bfloat16* __restrict__ Kl,
       const __nv_bfloat16* __restrict__ Vth, const __nv_bfloat16* __restrict__ Vtl,
       const float* __restrict__ gate, __nv_bfloat16* __restrict__ AOh,
       __nv_bfloat16* __restrict__ AOl, float* __restrict__ ent)
{
    extern __shared__ __nv_bfloat16 sm[];
    const int tid = threadIdx.x, w = tid >> 5, lane = tid & 31;
    const int qt = (gridDim.x - 1) - blockIdx.x;   // heavy tiles first
    const int bh = blockIdx.y;
    const int q0 = qt * 128;
    const int ntk = qt + 1;
    const uint32_t sb = smem_u32(sm);

    // load Q hi/lo (once)
    {
        const __nv_bfloat16* qh = Qh + ((size_t)bh*Nc + q0)*DHc;
        const __nv_bfloat16* ql = Ql + ((size_t)bh*Nc + q0)*DHc;
        #pragma unroll
        for (int i = tid; i < 1024; i += 256) {
            const int r = i >> 3, c = i & 7;
            *(uint4*)&sm[OQ_H + r*QS + c*8] = *(const uint4*)&qh[r*64 + c*8];
            *(uint4*)&sm[OQ_L + r*QS + c*8] = *(const uint4*)&ql[r*64 + c*8];
        }
    }

    const int g = lane >> 2;
    float m0 = -1e30f, m1 = -1e30f, l0 = 0.f, l1 = 0.f;
    float sacc[16][4];

    // ---------------- phase 1: online (m, l) ----------------
    for (int kt = 0; kt < ntk; kt++) {
        __syncthreads();
        {
            const __nv_bfloat16* kh = Kh + ((size_t)bh*Nc + kt*128)*DHc;
            const __nv_bfloat16* kl = Kl + ((size_t)bh*Nc + kt*128)*DHc;
            #pragma unroll
            for (int i = tid; i < 1024; i += 256) {
                const int r = i >> 3, c = i & 7;
                *(uint4*)&sm[OK_H + r*QS + c*8] = *(const uint4*)&kh[r*64 + c*8];
                *(uint4*)&sm[OK_L + r*QS + c*8] = *(const uint4*)&kl[r*64 + c*8];
            }
        }
        __syncthreads();
        attn_S(sb, w, lane, sacc);
        if (kt == qt) {
            #pragma unroll
            for (int nt = 0; nt < 16; nt++) {
                const int c0 = nt*8 + (lane & 3)*2;
                if (c0     > 16*w + g)     sacc[nt][0] = -1e30f;
                if (c0 + 1 > 16*w + g)     sacc[nt][1] = -1e30f;
                if (c0     > 16*w + g + 8) sacc[nt][2] = -1e30f;
                if (c0 + 1 > 16*w + g + 8) sacc[nt][3] = -1e30f;
            }
        }
        float mt0 = -1e30f, mt1 = -1e30f;
        #pragma unroll
        for (int nt = 0; nt < 16; nt++) {
            mt0 = fmaxf(mt0, fmaxf(sacc[nt][0], sacc[nt][1]));
            mt1 = fmaxf(mt1, fmaxf(sacc[nt][2], sacc[nt][3]));
        }
        mt0 = fmaxf(mt0, __shfl_xor_sync(0xffffffffu, mt0, 1));
        mt0 = fmaxf(mt0, __shfl_xor_sync(0xffffffffu, mt0, 2));
        mt1 = fmaxf(mt1, __shfl_xor_sync(0xffffffffu, mt1, 1));
        mt1 = fmaxf(mt1, __shfl_xor_sync(0xffffffffu, mt1, 2));
        const float mn0 = fmaxf(m0, mt0), mn1 = fmaxf(m1, mt1);
        float s0 = 0.f, s1 = 0.f;
        #pragma unroll
        for (int nt = 0; nt < 16; nt++) {
            s0 += __expf(sacc[nt][0]-mn0) + __expf(sacc[nt][1]-mn0);
            s1 += __expf(sacc[nt][2]-mn1) + __expf(sacc[nt][3]-mn1);
        }
        s0 += __shfl_xor_sync(0xffffffffu, s0, 1);
        s0 += __shfl_xor_sync(0xffffffffu, s0, 2);
        s1 += __shfl_xor_sync(0xffffffffu, s1, 1);
        s1 += __shfl_xor_sync(0xffffffffu, s1, 2);
        l0 = l0*__expf(m0 - mn0) + s0;  m0 = mn0;
        l1 = l1*__expf(m1 - mn1) + s1;  m1 = mn1;
    }

    // ---------------- phase 2: recompute S, p, entropy, P@V ----------------
    const float il0 = 1.f / l0, il1 = 1.f / l1;
    float e0 = 0.f, e1 = 0.f;
    float oacc[8][4];
    #pragma unroll
    for (int nt = 0; nt < 8; nt++)
        #pragma unroll
        for (int v = 0; v < 4; v++) oacc[nt][v] = 0.f;

    for (int kt = 0; kt < ntk; kt++) {
        __syncthreads();
        {
            const __nv_bfloat16* kh = Kh + ((size_t)bh*Nc + kt*128)*DHc;
            const __nv_bfloat16* kl = Kl + ((size_t)bh*Nc + kt*128)*DHc;
            #pragma unroll
            for (int i = tid; i < 1024; i += 256) {
                const int r = i >> 3, c = i & 7;
                *(uint4*)&sm[OK_H + r*QS + c*8] = *(const uint4*)&kh[r*64 + c*8];
                *(uint4*)&sm[OK_L + r*QS + c*8] = *(const uint4*)&kl[r*64 + c*8];
            }
            #pragma unroll
            for (int i = tid; i < 1024; i += 256) {
                const int r = i >> 4, c = i & 15;
                const size_t ad = ((size_t)bh*DHc + r)*Nc + kt*128 + c*8;
                *(uint4*)&sm[OV_H + r*PS + c*8] = *(const uint4*)&Vth[ad];
                *(uint4*)&sm[OV_L + r*PS + c*8] = *(const uint4*)&Vtl[ad];
            }
        }
        __syncthreads();
        attn_S(sb, w, lane, sacc);
        if (kt == qt) {
            #pragma unroll
            for (int nt = 0; nt < 16; nt++) {
                const int c0 = nt*8 + (lane & 3)*2;
                if (c0     > 16*w + g)     sacc[nt][0] = -1e30f;
                if (c0 + 1 > 16*w + g)     sacc[nt][1] = -1e30f;
                if (c0     > 16*w + g + 8) sacc[nt][2] = -1e30f;
                if (c0 + 1 > 16*w + g + 8) sacc[nt][3] = -1e30f;
            }
        }
        const int pr0 = 16*w + g, pr1 = pr0 + 8;
        #pragma unroll
        for (int nt = 0; nt < 16; nt++) {
            const int c0 = nt*8 + (lane & 3)*2;
            const float p00 = __expf(sacc[nt][0]-m0)*il0;
            const float p01 = __expf(sacc[nt][1]-m0)*il0;
            const float p10 = __expf(sacc[nt][2]-m1)*il1;
            const float p11 = __expf(sacc[nt][3]-m1)*il1;
            e0 += p00*__logf(p00 + 1e-6f) + p01*__logf(p01 + 1e-6f);
            e1 += p10*__logf(p10 + 1e-6f) + p11*__logf(p11 + 1e-6f);
            __nv_bfloat162 lo0, lo1;
            __nv_bfloat162 hi0 = split2(p00, p01, lo0);
            __nv_bfloat162 hi1 = split2(p10, p11, lo1);
            *(__nv_bfloat162*)&sm[OP_H + pr0*PS + c0] = hi0;
            *(__nv_bfloat162*)&sm[OP_L + pr0*PS + c0] = lo0;
            *(__nv_bfloat162*)&sm[OP_H + pr1*PS + c0] = hi1;
            *(__nv_bfloat162*)&sm[OP_L + pr1*PS + c0] = lo1;
        }
        __syncthreads();
        #pragma unroll
        for (int ks = 0; ks < 8; ks++) {
            const int ar = 16*w + (lane & 7) + ((lane >> 3) & 1)*8;
            const int ac = ks*16 + (lane >> 4)*8;
            uint32_t ah[4], al[4];
            LDSM4(ah[0], ah[1], ah[2], ah[3], sb + (uint32_t)(OP_H + ar*PS + ac)*2);
            LDSM4(al[0], al[1], al[2], al[3], sb + (uint32_t)(OP_L + ar*PS + ac)*2);
            #pragma unroll
            for (int np = 0; np < 4; np++) {
                const int br = np*16 + ((lane >> 4) & 1)*8 + (lane & 7);
                const int bc = ks*16 + ((lane >> 3) & 1)*8;
                uint32_t bh4[4], bl4[4];
                LDSM4(bh4[0], bh4[1], bh4[2], bh4[3], sb + (uint32_t)(OV_H + br*PS + bc)*2);
                LDSM4(bl4[0], bl4[1], bl4[2], bl4[3], sb + (uint32_t)(OV_L + br*PS + bc)*2);
                MMA16816(oacc[2*np],   ah, bh4[0], bh4[1]);
                MMA16816(oacc[2*np],   ah, bl4[0], bl4[1]);
                MMA16816(oacc[2*np],   al, bh4[0], bh4[1]);
                MMA16816(oacc[2*np+1], ah, bh4[2], bh4[3]);
                MMA16816(oacc[2*np+1], ah, bl4[2], bl4[3]);
                MMA16816(oacc[2*np+1], al, bh4[2], bh4[3]);
            }
        }
    }

    // ---------------- epilogue ----------------
    e0 += __shfl_xor_sync(0xffffffffu, e0, 1);
    e0 += __shfl_xor_sync(0xffffffffu, e0, 2);
    e1 += __shfl_xor_sync(0xffffffffu, e1, 1);
    e1 += __shfl_xor_sync(0xffffffffu, e1, 2);
    const int b = bh >> 4, h = bh & 15;
    const int qg0 = q0 + 16*w + g, qg1 = qg0 + 8;
    if ((lane & 3) == 0) {
        ent[(size_t)bh*Nc + qg0] = -e0;
        ent[(size_t)bh*Nc + qg1] = -e1;
    }
    const float gt0 = gate[(size_t)b*Nc + qg0];
    const float gt1 = gate[(size_t)b*Nc + qg1];
    #pragma unroll
    for (int nt = 0; nt < 8; nt++) {
        const int c = h*64 + nt*8 + (lane & 3)*2;
        const size_t a0 = ((size_t)(b*Nc + qg0))*Dc + c;
        const size_t a1 = ((size_t)(b*Nc + qg1))*Dc + c;
        __nv_bfloat162 lo0, lo1;
        __nv_bfloat162 hi0 = split2(oacc[nt][0]*gt0, oacc[nt][1]*gt0, lo0);
        __nv_bfloat162 hi1 = split2(oacc[nt][2]*gt1, oacc[nt][3]*gt1, lo1);
        *(__nv_bfloat162*)&AOh[a0] = hi0;
        *(__nv_bfloat162*)&AOl[a0] = lo0;
        *(__nv_bfloat162*)&AOh[a1] = hi1;
        *(__nv_bfloat162*)&AOl[a1] = lo1;
    }
}

// ---------------------------------------------------------------------------
extern "C" void kernel_launch(void* const* d_in, const int* in_sizes, int n_in,
                              void* d_out, int out_size)
{
    const float* x   = (const float*)d_in[0];
    const float* Wq  = (const float*)d_in[2];
    const float* bq  = (const float*)d_in[3];
    const float* Wk  = (const float*)d_in[4];
    const float* bk  = (const float*)d_in[5];
    const float* Wv  = (const float*)d_in[6];
    const float* bv  = (const float*)d_in[7];
    const float* Wg1 = (const float*)d_in[8];
    const float* bg1 = (const float*)d_in[9];
    const float* Wg2 = (const float*)d_in[10];
    const float* bg2 = (const float*)d_in[11];
    const float* Wo  = (const float*)d_in[12];
    const float* bo  = (const float*)d_in[13];

    float* out = (float*)d_out;                       // [B, N, D]
    float* ent = out + (size_t)Bc*Nc*Dc;              // [B, H, N]

    float *Vp, *G1p, *Gp;
    __nv_bfloat16 *xh, *xl, *qh, *ql, *kh, *kl, *vth, *vtl, *AOh, *AOl, *Wth, *Wtl;
    cudaGetSymbolAddress((void**)&Vp,  g_V);
    cudaGetSymbolAddress((void**)&G1p, g_G1);
    cudaGetSymbolAddress((void**)&Gp,  g_gate);
    cudaGetSymbolAddress((void**)&xh,  g_xh);
    cudaGetSymbolAddress((void**)&xl,  g_xl);
    cudaGetSymbolAddress((void**)&qh,  g_qh);
    cudaGetSymbolAddress((void**)&ql,  g_ql);
    cudaGetSymbolAddress((void**)&kh,  g_kh);
    cudaGetSymbolAddress((void**)&kl,  g_kl);
    cudaGetSymbolAddress((void**)&vth, g_vth);
    cudaGetSymbolAddress((void**)&vtl, g_vtl);
    cudaGetSymbolAddress((void**)&AOh, g_AOh);
    cudaGetSymbolAddress((void**)&AOl, g_AOl);
    cudaGetSymbolAddress((void**)&Wth, g_Wth);
    cudaGetSymbolAddress((void**)&Wtl, g_Wtl);

    const int TCSMEM = 2 * 4 * 128 * KSTR * 2;     // 81920
    cudaFuncSetAttribute(tc_gemm<0>, cudaFuncAttributeMaxDynamicSharedMemorySize, TCSMEM);
    cudaFuncSetAttribute(tc_gemm<1>, cudaFuncAttributeMaxDynamicSharedMemorySize, TCSMEM);
    cudaFuncSetAttribute(tc_gemm<2>, cudaFuncAttributeMaxDynamicSharedMemorySize, TCSMEM);
    cudaFuncSetAttribute(tc_gemm<3>, cudaFuncAttributeMaxDynamicSharedMemorySize, TCSMEM);
    cudaFuncSetAttribute(attn_k, cudaFuncAttributeMaxDynamicSharedMemorySize, ATT_SMEM_B);

    split_k<<<Mc*Dc/4/256, 256>>>(x, xh, xl, Mc*Dc/4);
    dim3 gt(32, 32);
    tsplit_k<<<gt, 256>>>(Wq,  Wth + 0*(size_t)Dc*Dc, Wtl + 0*(size_t)Dc*Dc);
    tsplit_k<<<gt, 256>>>(Wk,  Wth + 1*(size_t)Dc*Dc, Wtl + 1*(size_t)Dc*Dc);
    tsplit_k<<<gt, 256>>>(Wv,  Wth + 2*(size_t)Dc*Dc, Wtl + 2*(size_t)Dc*Dc);
    tsplit_k<<<gt, 256>>>(Wg1, Wth + 3*(size_t)Dc*Dc, Wtl + 3*(size_t)Dc*Dc);
    tsplit_k<<<gt, 256>>>(Wo,  Wth + 4*(size_t)Dc*Dc, Wtl + 4*(size_t)Dc*Dc);

    dim3 gg(Dc/128, Mc/128);   // (8, 24)
    tc_gemm<3><<<gg, 256, TCSMEM>>>(xh, xl, Wth + 0*(size_t)Dc*Dc, Wtl + 0*(size_t)Dc*Dc,
                                    bq, nullptr, qh, ql, 0.125f);
    tc_gemm<3><<<gg, 256, TCSMEM>>>(xh, xl, Wth + 1*(size_t)Dc*Dc, Wtl + 1*(size_t)Dc*Dc,
                                    bk, nullptr, kh, kl, 1.f);
    tc_gemm<1><<<gg, 256, TCSMEM>>>(xh, xl, Wth + 2*(size_t)Dc*Dc, Wtl + 2*(size_t)Dc*Dc,
                                    bv, Vp, nullptr, nullptr, 1.f);
    tc_gemm<2><<<gg, 256, TCSMEM>>>(xh, xl, Wth + 3*(size_t)Dc*Dc, Wtl + 3*(size_t)Dc*Dc,
                                    bg1, G1p, nullptr, nullptr, 1.f);

    vt_k<<<dim3(Nc/32, DHc/32, BHc), 256>>>(Vp, vth, vtl);
    gate_k<<<Mc, 256>>>(G1p, Wg2, bg2, Gp);

    attn_k<<<dim3(Nc/128, BHc), 256, ATT_SMEM_B>>>(qh, ql, kh, kl, vth, vtl,
                                                   Gp, AOh, AOl, ent);

    tc_gemm<0><<<gg, 256, TCSMEM>>>(AOh, AOl, Wth + 4*(size_t)Dc*Dc, Wtl + 4*(size_t)Dc*Dc,
                                    bo, out, nullptr, nullptr, 1.f);
}

// round 7
// speedup vs baseline: 3.6112x; 1.1911x over previous
#include <cuda_runtime.h>
#include <cuda_bf16.h>
#include <math.h>
#include <stdint.h>

#define Bc 2
#define Nc 1536
#define Dc 1024
#define Hc 16
#define DHc 64
#define Mc (Bc*Nc)
#define BHc (Bc*Hc)
#define KSTR 40     // gemm bf16 smem row stride (80B -> ldmatrix conflict-free)

// attention smem geometry (bf16 element offsets)
#define QS 72       // 64-wide tiles padded: 144B = 9*16B
#define PS 136      // 128-wide tiles padded: 272B = 17*16B
#define OQ_H 0
#define OQ_L 9216
#define OK_H 18432
#define OK_L 27648
#define OV_H 36864
#define OV_L 45568
#define OP_H 54272
#define OP_L 71680
#define ATT_SMEM_B (89088*2)

// ---------------- scratch (allocation-free rule: device globals) ------------
__device__ float g_V[BHc*Nc*DHc];
__device__ float g_G1[Mc*Dc];
__device__ float g_gate[Mc];
__device__ __nv_bfloat16 g_xh[Mc*Dc],  g_xl[Mc*Dc];
__device__ __nv_bfloat16 g_qh[BHc*Nc*DHc], g_ql[BHc*Nc*DHc];
__device__ __nv_bfloat16 g_kh[BHc*Nc*DHc], g_kl[BHc*Nc*DHc];
__device__ __nv_bfloat16 g_vth[BHc*DHc*Nc], g_vtl[BHc*DHc*Nc];  // [bh][dh][n]
__device__ __nv_bfloat16 g_AOh[Mc*Dc], g_AOl[Mc*Dc];
__device__ __nv_bfloat16 g_Wth[5][Dc*Dc], g_Wtl[5][Dc*Dc];      // [n][k]

struct WPtrs  { const float* w[5]; };
struct BPtrs  { const float* b[4]; };

// ---------------- PTX helpers ----------------------------------------------
static __device__ __forceinline__ uint32_t smem_u32(const void* p) {
    uint32_t a;
    asm("{ .reg .u64 t; cvta.to.shared.u64 t, %1; cvt.u32.u64 %0, t; }"
        : "=r"(a) : "l"(p));
    return a;
}
#define LDSM4(r0, r1, r2, r3, addr) \
    asm volatile("ldmatrix.sync.aligned.m8n8.x4.shared.b16 {%0,%1,%2,%3}, [%4];" \
                 : "=r"(r0), "=r"(r1), "=r"(r2), "=r"(r3) : "r"(addr))
#define MMA16816(d, a, b0, b1) \
    asm volatile("mma.sync.aligned.m16n8k16.row.col.f32.bf16.bf16.f32 " \
                 "{%0,%1,%2,%3}, {%4,%5,%6,%7}, {%8,%9}, {%0,%1,%2,%3};" \
                 : "+f"((d)[0]), "+f"((d)[1]), "+f"((d)[2]), "+f"((d)[3]) \
                 : "r"((a)[0]), "r"((a)[1]), "r"((a)[2]), "r"((a)[3]), \
                   "r"(b0), "r"(b1))
static __device__ __forceinline__ void cp_async16(uint32_t saddr, const void* gptr) {
    asm volatile("{ .reg .u64 g; cvta.to.global.u64 g, %1; "
                 "cp.async.cg.shared.global [%0], [g], 16; }"
                 :: "r"(saddr), "l"(gptr) : "memory");
}
#define CP_COMMIT() asm volatile("cp.async.commit_group;" ::: "memory")
#define CP_WAIT(n)  asm volatile("cp.async.wait_group %0;" :: "n"(n) : "memory")

static __device__ __forceinline__ __nv_bfloat162 split2(float a, float b,
                                                        __nv_bfloat162& lo) {
    __nv_bfloat16 ha = __float2bfloat16(a), hb = __float2bfloat16(b);
    lo.x = __float2bfloat16(a - __bfloat162float(ha));
    lo.y = __float2bfloat16(b - __bfloat162float(hb));
    __nv_bfloat162 hi; hi.x = ha; hi.y = hb;
    return hi;
}

// ---------------------------------------------------------------------------
// HMMA GEMM mainloop (shared by both gemm kernels): 128x128 tile, split-bf16
// 3-term, K-tile 32, cp.async double buffer. Leaves result in acc.
// ---------------------------------------------------------------------------
static __device__ __forceinline__ void gemm_main(
    const __nv_bfloat16* __restrict__ Ah, const __nv_bfloat16* __restrict__ Al,
    const __nv_bfloat16* __restrict__ Bh, const __nv_bfloat16* __restrict__ Bl,
    int m0, int n0, uint32_t sb, int tid, int wr, int wc, int lane,
    float acc[4][4][4])
{
    const int TILE_B = 128 * KSTR * 2;
    #pragma unroll
    for (int m = 0; m < 4; m++)
        #pragma unroll
        for (int n = 0; n < 4; n++)
            #pragma unroll
            for (int v = 0; v < 4; v++) acc[m][n][v] = 0.f;

    auto issue = [&](int kt, int stg) {
        const int k0 = kt * 32;
        const uint32_t so = sb + stg * 4 * TILE_B;
        #pragma unroll
        for (int j = 0; j < 2; j++) {
            const int cid = tid + j * 256;
            const int r = cid >> 2, c = cid & 3;
            const uint32_t soff = (uint32_t)(r * KSTR + c * 8) * 2;
            const size_t ga = (size_t)(m0 + r) * Dc + k0 + c * 8;
            const size_t gb = (size_t)(n0 + r) * Dc + k0 + c * 8;
            cp_async16(so + soff,              Ah + ga);
            cp_async16(so + TILE_B + soff,     Al + ga);
            cp_async16(so + 2 * TILE_B + soff, Bh + gb);
            cp_async16(so + 3 * TILE_B + soff, Bl + gb);
        }
    };

    issue(0, 0);
    CP_COMMIT();

    for (int kt = 0; kt < 32; kt++) {
        const int stg = kt & 1;
        if (kt + 1 < 32) { issue(kt + 1, stg ^ 1); CP_COMMIT(); CP_WAIT(1); }
        else             { CP_WAIT(0); }
        __syncthreads();

        const uint32_t so  = sb + stg * 4 * TILE_B;
        const uint32_t aAh = so,            aAl = so + TILE_B;
        const uint32_t aBh = so + 2*TILE_B, aBl = so + 3*TILE_B;

        #pragma unroll
        for (int ks = 0; ks < 2; ks++) {
            const int k0 = ks * 16;
            uint32_t bhf[8], blf[8];
            #pragma unroll
            for (int pr = 0; pr < 2; pr++) {
                const int row = wc*32 + pr*16 + ((lane >> 4) & 1)*8 + (lane & 7);
                const int col = k0 + ((lane >> 3) & 1)*8;
                const uint32_t off = (uint32_t)(row * KSTR + col) * 2;
                LDSM4(bhf[pr*4+0], bhf[pr*4+1], bhf[pr*4+2], bhf[pr*4+3], aBh + off);
                LDSM4(blf[pr*4+0], blf[pr*4+1], blf[pr*4+2], blf[pr*4+3], aBl + off);
            }
            #pragma unroll
            for (int m = 0; m < 4; m++) {
                const int row = wr*64 + m*16 + (lane & 7) + ((lane >> 3) & 1)*8;
                const int col = k0 + (lane >> 4)*8;
                const uint32_t off = (uint32_t)(row * KSTR + col) * 2;
                uint32_t ah[4], al[4];
                LDSM4(ah[0], ah[1], ah[2], ah[3], aAh + off);
                LDSM4(al[0], al[1], al[2], al[3], aAl + off);
                #pragma unroll
                for (int n = 0; n < 4; n++) {
                    MMA16816(acc[m][n], ah, bhf[n*2], bhf[n*2+1]);
                    MMA16816(acc[m][n], ah, blf[n*2], blf[n*2+1]);
                    MMA16816(acc[m][n], al, bhf[n*2], bhf[n*2+1]);
                }
            }
        }
        __syncthreads();
    }
}

// ---------------------------------------------------------------------------
// Fused Q/K/V/G1 projection GEMM. blockIdx.z selects weight set + epilogue:
// z=0: Q -> split bf16 scatter, scale 1/8;  z=1: K -> split bf16 scatter;
// z=2: V -> fp32 scatter;                   z=3: G1 -> exact GELU fp32.
// ---------------------------------------------------------------------------
__global__ void __launch_bounds__(256, 2)
proj_gemm(const __nv_bfloat16* __restrict__ xh, const __nv_bfloat16* __restrict__ xl,
          const __nv_bfloat16* __restrict__ Wth, const __nv_bfloat16* __restrict__ Wtl,
          BPtrs bp, float* __restrict__ Vout, float* __restrict__ G1out,
          __nv_bfloat16* __restrict__ qh, __nv_bfloat16* __restrict__ ql,
          __nv_bfloat16* __restrict__ kh, __nv_bfloat16* __restrict__ kl)
{
    extern __shared__ __nv_bfloat16 sm[];
    const int tid = threadIdx.x, wid = tid >> 5, lane = tid & 31;
    const int m0 = blockIdx.y * 128, n0 = blockIdx.x * 128;
    const int z = blockIdx.z;
    const int wr = wid & 1, wc = wid >> 1;
    const uint32_t sb = smem_u32(sm);
    const float* bias = bp.b[z];

    float acc[4][4][4];
    gemm_main(xh, xl, Wth + (size_t)z*Dc*Dc, Wtl + (size_t)z*Dc*Dc,
              m0, n0, sb, tid, wr, wc, lane, acc);

    const float scale = (z == 0) ? 0.125f : 1.f;
    #pragma unroll
    for (int m = 0; m < 4; m++) {
        #pragma unroll
        for (int n = 0; n < 4; n++) {
            const int c = n0 + wc*32 + n*8 + (lane & 3)*2;
            const float b0 = bias[c], b1 = bias[c + 1];
            #pragma unroll
            for (int hv = 0; hv < 2; hv++) {
                const int r = m0 + wr*64 + m*16 + (lane >> 2) + hv*8;
                float v0 = acc[m][n][hv*2+0] + b0;
                float v1 = acc[m][n][hv*2+1] + b1;
                if (z <= 1) {
                    const int bb = r / Nc, nn = r % Nc;
                    const int h = c >> 6, dh = c & 63;
                    const size_t ad = (((size_t)(bb*Hc + h))*Nc + nn)*DHc + dh;
                    __nv_bfloat162 lo;
                    __nv_bfloat162 hi = split2(v0*scale, v1*scale, lo);
                    if (z == 0) {
                        *(__nv_bfloat162*)&qh[ad] = hi;
                        *(__nv_bfloat162*)&ql[ad] = lo;
                    } else {
                        *(__nv_bfloat162*)&kh[ad] = hi;
                        *(__nv_bfloat162*)&kl[ad] = lo;
                    }
                } else if (z == 2) {
                    const int bb = r / Nc, nn = r % Nc;
                    const int h = c >> 6, dh = c & 63;
                    float2 o = {v0, v1};
                    *(float2*)&Vout[(((size_t)(bb*Hc + h))*Nc + nn)*DHc + dh] = o;
                } else {
                    float2 o;
                    o.x = 0.5f*v0*(1.f + erff(v0*0.70710678118654752f));
                    o.y = 0.5f*v1*(1.f + erff(v1*0.70710678118654752f));
                    *(float2*)&G1out[(size_t)r*Dc + c] = o;
                }
            }
        }
    }
}

// ---------------------------------------------------------------------------
// Output projection GEMM: out = AO @ Wo^T + bo (fp32 out)
// ---------------------------------------------------------------------------
__global__ void __launch_bounds__(256, 2)
out_gemm(const __nv_bfloat16* __restrict__ Ah, const __nv_bfloat16* __restrict__ Al,
         const __nv_bfloat16* __restrict__ Bh, const __nv_bfloat16* __restrict__ Bl,
         const float* __restrict__ bias, float* __restrict__ C)
{
    extern __shared__ __nv_bfloat16 sm[];
    const int tid = threadIdx.x, wid = tid >> 5, lane = tid & 31;
    const int m0 = blockIdx.y * 128, n0 = blockIdx.x * 128;
    const int wr = wid & 1, wc = wid >> 1;
    const uint32_t sb = smem_u32(sm);

    float acc[4][4][4];
    gemm_main(Ah, Al, Bh, Bl, m0, n0, sb, tid, wr, wc, lane, acc);

    #pragma unroll
    for (int m = 0; m < 4; m++) {
        #pragma unroll
        for (int n = 0; n < 4; n++) {
            const int c = n0 + wc*32 + n*8 + (lane & 3)*2;
            const float b0 = bias[c], b1 = bias[c + 1];
            #pragma unroll
            for (int hv = 0; hv < 2; hv++) {
                const int r = m0 + wr*64 + m*16 + (lane >> 2) + hv*8;
                float2 o = {acc[m][n][hv*2+0] + b0, acc[m][n][hv*2+1] + b1};
                *(float2*)&C[(size_t)r*Dc + c] = o;
            }
        }
    }
}

// ---------------------------------------------------------------------------
// fp32 -> bf16 hi/lo split
// ---------------------------------------------------------------------------
__global__ void split_k(const float* __restrict__ in, __nv_bfloat16* __restrict__ hi,
                        __nv_bfloat16* __restrict__ lo, int n4)
{
    const int i = blockIdx.x * 256 + threadIdx.x;
    if (i >= n4) return;
    float4 v = ((const float4*)in)[i];
    __nv_bfloat162 L0, L1;
    __nv_bfloat162 H0 = split2(v.x, v.y, L0);
    __nv_bfloat162 H1 = split2(v.z, v.w, L1);
    ((__nv_bfloat162*)hi)[i * 2 + 0] = H0;
    ((__nv_bfloat162*)hi)[i * 2 + 1] = H1;
    ((__nv_bfloat162*)lo)[i * 2 + 0] = L0;
    ((__nv_bfloat162*)lo)[i * 2 + 1] = L1;
}

// ---------------------------------------------------------------------------
// Weight transpose + split, all 5 weights in one launch (z selects matrix)
// ---------------------------------------------------------------------------
__global__ void tsplit_k(WPtrs wp, __nv_bfloat16* __restrict__ th,
                         __nv_bfloat16* __restrict__ tl)
{
    __shared__ float t[32][33];
    const int z = blockIdx.z;
    const float* W = wp.w[z];
    th += (size_t)z * Dc * Dc;
    tl += (size_t)z * Dc * Dc;
    const int k0 = blockIdx.y * 32, n0 = blockIdx.x * 32;
    const int lane = threadIdx.x & 31, wr = threadIdx.x >> 5;
    #pragma unroll
    for (int i = 0; i < 4; i++)
        t[wr + i * 8][lane] = W[(size_t)(k0 + wr + i * 8) * Dc + n0 + lane];
    __syncthreads();
    #pragma unroll
    for (int i = 0; i < 4; i++) {
        float v = t[lane][wr + i * 8];
        __nv_bfloat16 h = __float2bfloat16(v);
        th[(size_t)(n0 + wr + i * 8) * Dc + k0 + lane] = h;
        tl[(size_t)(n0 + wr + i * 8) * Dc + k0 + lane] =
            __float2bfloat16(v - __bfloat162float(h));
    }
}

// ---------------------------------------------------------------------------
// V transpose + split: V[bh][n][dh] fp32 -> Vt[bh][dh][n] bf16 hi/lo
// ---------------------------------------------------------------------------
__global__ void vt_k(const float* __restrict__ V, __nv_bfloat16* __restrict__ th,
                     __nv_bfloat16* __restrict__ tl)
{
    __shared__ float t[32][33];
    const int bh = blockIdx.z;
    const int n0 = blockIdx.x * 32, d0 = blockIdx.y * 32;
    const int lane = threadIdx.x & 31, wr = threadIdx.x >> 5;
    #pragma unroll
    for (int i = 0; i < 4; i++)
        t[wr + i * 8][lane] = V[((size_t)bh*Nc + n0 + wr + i*8)*DHc + d0 + lane];
    __syncthreads();
    #pragma unroll
    for (int i = 0; i < 4; i++) {
        float v = t[lane][wr + i * 8];
        __nv_bfloat16 h = __float2bfloat16(v);
        const size_t ad = ((size_t)bh*DHc + d0 + wr + i*8)*Nc + n0 + lane;
        th[ad] = h;
        tl[ad] = __float2bfloat16(v - __bfloat162float(h));
    }
}

// ---------------------------------------------------------------------------
// Gate: gate[r] = sigmoid( dot(G1[r,:], Wg2) + bg2 )
// ---------------------------------------------------------------------------
__global__ void gate_k(const float* __restrict__ G1, const float* __restrict__ Wg2,
                       const float* __restrict__ bg2, float* __restrict__ gate)
{
    __shared__ float red[256];
    const int r = blockIdx.x;
    float s = 0.f;
    for (int k = threadIdx.x; k < Dc; k += 256)
        s += G1[(size_t)r*Dc + k] * Wg2[k];
    red[threadIdx.x] = s;
    __syncthreads();
    for (int o = 128; o; o >>= 1) {
        if (threadIdx.x < o) red[threadIdx.x] += red[threadIdx.x + o];
        __syncthreads();
    }
    if (threadIdx.x == 0) {
        float z = red[0] + bg2[0];
        gate[r] = 1.f / (1.f + expf(-z));
    }
}

// ---------------------------------------------------------------------------
// Fused causal attention (HMMA split-bf16, recompute-S).
// ---------------------------------------------------------------------------
__device__ __forceinline__ void attn_S(uint32_t sb, int w, int lane, float sacc[16][4])
{
    #pragma unroll
    for (int nt = 0; nt < 16; nt++)
        #pragma unroll
        for (int v = 0; v < 4; v++) sacc[nt][v] = 0.f;
    #pragma unroll
    for (int ks = 0; ks < 4; ks++) {
        const int ar = 16*w + (lane & 7) + ((lane >> 3) & 1)*8;
        const int ac = ks*16 + (lane >> 4)*8;
        uint32_t ah[4], al[4];
        LDSM4(ah[0], ah[1], ah[2], ah[3], sb + (uint32_t)(OQ_H + ar*QS + ac)*2);
        LDSM4(al[0], al[1], al[2], al[3], sb + (uint32_t)(OQ_L + ar*QS + ac)*2);
        #pragma unroll
        for (int np = 0; np < 8; np++) {
            const int br = np*16 + ((lane >> 4) & 1)*8 + (lane & 7);
            const int bc = ks*16 + ((lane >> 3) & 1)*8;
            uint32_t bh4[4], bl4[4];
            LDSM4(bh4[0], bh4[1], bh4[2], bh4[3], sb + (uint32_t)(OK_H + br*QS + bc)*2);
            LDSM4(bl4[0], bl4[1], bl4[2], bl4[3], sb + (uint32_t)(OK_L + br*QS + bc)*2);
            MMA16816(sacc[2*np],   ah, bh4[0], bh4[1]);
            MMA16816(sacc[2*np],   ah, bl4[0], bl4[1]);
            MMA16816(sacc[2*np],   al, bh4[0], bh4[1]);
            MMA16816(sacc[2*np+1], ah, bh4[2], bh4[3]);
            MMA16816(sacc[2*np+1], ah, bl4[2], bl4[3]);
            MMA16816(sacc[2*np+1], al, bh4[2], bh4[3]);
        }
    }
}

__global__ void __launch_bounds__(256)
attn_k(const __nv_bfloat16* __restrict__ Qh, const __nv_bfloat16* __restrict__ Ql,
       const __nv_bfloat16* __restrict__ Kh, const __nv_bfloat16* __restrict__ Kl,
       const __nv_bfloat16* __restrict__ Vth, const __nv_bfloat16* __restrict__ Vtl,
       const float* __restrict__ gate, __nv_bfloat16* __restrict__ AOh,
       __nv_bfloat16* __restrict__ AOl, float* __restrict__ ent)
{
    extern __shared__ __nv_bfloat16 sm[];
    const int tid = threadIdx.x, w = tid >> 5, lane = tid & 31;
    const int qt = (gridDim.x - 1) - blockIdx.x;   // heavy tiles first
    const int bh = blockIdx.y;
    const int q0 = qt * 128;
    const int ntk = qt + 1;
    const uint32_t sb = smem_u32(sm);

    {
        const __nv_bfloat16* qh = Qh + ((size_t)bh*Nc + q0)*DHc;
        const __nv_bfloat16* ql = Ql + ((size_t)bh*Nc + q0)*DHc;
        #pragma unroll
        for (int i = tid; i < 1024; i += 256) {
            const int r = i >> 3, c = i & 7;
            *(uint4*)&sm[OQ_H + r*QS + c*8] = *(const uint4*)&qh[r*64 + c*8];
            *(uint4*)&sm[OQ_L + r*QS + c*8] = *(const uint4*)&ql[r*64 + c*8];
        }
    }

    const int g = lane >> 2;
    float m0 = -1e30f, m1 = -1e30f, l0 = 0.f, l1 = 0.f;
    float sacc[16][4];

    // ---------------- phase 1: online (m, l) ----------------
    for (int kt = 0; kt < ntk; kt++) {
        __syncthreads();
        {
            const __nv_bfloat16* kh = Kh + ((size_t)bh*Nc + kt*128)*DHc;
            const __nv_bfloat16* kl = Kl + ((size_t)bh*Nc + kt*128)*DHc;
            #pragma unroll
            for (int i = tid; i < 1024; i += 256) {
                const int r = i >> 3, c = i & 7;
                *(uint4*)&sm[OK_H + r*QS + c*8] = *(const uint4*)&kh[r*64 + c*8];
                *(uint4*)&sm[OK_L + r*QS + c*8] = *(const uint4*)&kl[r*64 + c*8];
            }
        }
        __syncthreads();
        attn_S(sb, w, lane, sacc);
        if (kt == qt) {
            #pragma unroll
            for (int nt = 0; nt < 16; nt++) {
                const int c0 = nt*8 + (lane & 3)*2;
                if (c0     > 16*w + g)     sacc[nt][0] = -1e30f;
                if (c0 + 1 > 16*w + g)     sacc[nt][1] = -1e30f;
                if (c0     > 16*w + g + 8) sacc[nt][2] = -1e30f;
                if (c0 + 1 > 16*w + g + 8) sacc[nt][3] = -1e30f;
            }
        }
        float mt0 = -1e30f, mt1 = -1e30f;
        #pragma unroll
        for (int nt = 0; nt < 16; nt++) {
            mt0 = fmaxf(mt0, fmaxf(sacc[nt][0], sacc[nt][1]));
            mt1 = fmaxf(mt1, fmaxf(sacc[nt][2], sacc[nt][3]));
        }
        mt0 = fmaxf(mt0, __shfl_xor_sync(0xffffffffu, mt0, 1));
        mt0 = fmaxf(mt0, __shfl_xor_sync(0xffffffffu, mt0, 2));
        mt1 = fmaxf(mt1, __shfl_xor_sync(0xffffffffu, mt1, 1));
        mt1 = fmaxf(mt1, __shfl_xor_sync(0xffffffffu, mt1, 2));
        const float mn0 = fmaxf(m0, mt0), mn1 = fmaxf(m1, mt1);
        float s0 = 0.f, s1 = 0.f;
        #pragma unroll
        for (int nt = 0; nt < 16; nt++) {
            s0 += __expf(sacc[nt][0]-mn0) + __expf(sacc[nt][1]-mn0);
            s1 += __expf(sacc[nt][2]-mn1) + __expf(sacc[nt][3]-mn1);
        }
        s0 += __shfl_xor_sync(0xffffffffu, s0, 1);
        s0 += __shfl_xor_sync(0xffffffffu, s0, 2);
        s1 += __shfl_xor_sync(0xffffffffu, s1, 1);
        s1 += __shfl_xor_sync(0xffffffffu, s1, 2);
        l0 = l0*__expf(m0 - mn0) + s0;  m0 = mn0;
        l1 = l1*__expf(m1 - mn1) + s1;  m1 = mn1;
    }

    // ---------------- phase 2: recompute S, p, entropy, P@V ----------------
    const float il0 = 1.f / l0, il1 = 1.f / l1;
    float e0 = 0.f, e1 = 0.f;
    float oacc[8][4];
    #pragma unroll
    for (int nt = 0; nt < 8; nt++)
        #pragma unroll
        for (int v = 0; v < 4; v++) oacc[nt][v] = 0.f;

    for (int kt = 0; kt < ntk; kt++) {
        __syncthreads();
        {
            const __nv_bfloat16* kh = Kh + ((size_t)bh*Nc + kt*128)*DHc;
            const __nv_bfloat16* kl = Kl + ((size_t)bh*Nc + kt*128)*DHc;
            #pragma unroll
            for (int i = tid; i < 1024; i += 256) {
                const int r = i >> 3, c = i & 7;
                *(uint4*)&sm[OK_H + r*QS + c*8] = *(const uint4*)&kh[r*64 + c*8];
                *(uint4*)&sm[OK_L + r*QS + c*8] = *(const uint4*)&kl[r*64 + c*8];
            }
            #pragma unroll
            for (int i = tid; i < 1024; i += 256) {
                const int r = i >> 4, c = i & 15;
                const size_t ad = ((size_t)bh*DHc + r)*Nc + kt*128 + c*8;
                *(uint4*)&sm[OV_H + r*PS + c*8] = *(const uint4*)&Vth[ad];
                *(uint4*)&sm[OV_L + r*PS + c*8] = *(const uint4*)&Vtl[ad];
            }
        }
        __syncthreads();
        attn_S(sb, w, lane, sacc);
        if (kt == qt) {
            #pragma unroll
            for (int nt = 0; nt < 16; nt++) {
                const int c0 = nt*8 + (lane & 3)*2;
                if (c0     > 16*w + g)     sacc[nt][0] = -1e30f;
                if (c0 + 1 > 16*w + g)     sacc[nt][1] = -1e30f;
                if (c0     > 16*w + g + 8) sacc[nt][2] = -1e30f;
                if (c0 + 1 > 16*w + g + 8) sacc[nt][3] = -1e30f;
            }
        }
        const int pr0 = 16*w + g, pr1 = pr0 + 8;
        #pragma unroll
        for (int nt = 0; nt < 16; nt++) {
            const int c0 = nt*8 + (lane & 3)*2;
            const float p00 = __expf(sacc[nt][0]-m0)*il0;
            const float p01 = __expf(sacc[nt][1]-m0)*il0;
            const float p10 = __expf(sacc[nt][2]-m1)*il1;
            const float p11 = __expf(sacc[nt][3]-m1)*il1;
            e0 += p00*__logf(p00 + 1e-6f) + p01*__logf(p01 + 1e-6f);
            e1 += p10*__logf(p10 + 1e-6f) + p11*__logf(p11 + 1e-6f);
            __nv_bfloat162 lo0, lo1;
            __nv_bfloat162 hi0 = split2(p00, p01, lo0);
            __nv_bfloat162 hi1 = split2(p10, p11, lo1);
            *(__nv_bfloat162*)&sm[OP_H + pr0*PS + c0] = hi0;
            *(__nv_bfloat162*)&sm[OP_L + pr0*PS + c0] = lo0;
            *(__nv_bfloat162*)&sm[OP_H + pr1*PS + c0] = hi1;
            *(__nv_bfloat162*)&sm[OP_L + pr1*PS + c0] = lo1;
        }
        __syncthreads();
        #pragma unroll
        for (int ks = 0; ks < 8; ks++) {
            const int ar = 16*w + (lane & 7) + ((lane >> 3) & 1)*8;
            const int ac = ks*16 + (lane >> 4)*8;
            uint32_t ah[4], al[4];
            LDSM4(ah[0], ah[1], ah[2], ah[3], sb + (uint32_t)(OP_H + ar*PS + ac)*2);
            LDSM4(al[0], al[1], al[2], al[3], sb + (uint32_t)(OP_L + ar*PS + ac)*2);
            #pragma unroll
            for (int np = 0; np < 4; np++) {
                const int br = np*16 + ((lane >> 4) & 1)*8 + (lane & 7);
                const int bc = ks*16 + ((lane >> 3) & 1)*8;
                uint32_t bh4[4], bl4[4];
                LDSM4(bh4[0], bh4[1], bh4[2], bh4[3], sb + (uint32_t)(OV_H + br*PS + bc)*2);
                LDSM4(bl4[0], bl4[1], bl4[2], bl4[3], sb + (uint32_t)(OV_L + br*PS + bc)*2);
                MMA16816(oacc[2*np],   ah, bh4[0], bh4[1]);
                MMA16816(oacc[2*np],   ah, bl4[0], bl4[1]);
                MMA16816(oacc[2*np],   al, bh4[0], bh4[1]);
                MMA16816(oacc[2*np+1], ah, bh4[2], bh4[3]);
                MMA16816(oacc[2*np+1], ah, bl4[2], bl4[3]);
                MMA16816(oacc[2*np+1], al, bh4[2], bh4[3]);
            }
        }
    }

    // ---------------- epilogue ----------------
    e0 += __shfl_xor_sync(0xffffffffu, e0, 1);
    e0 += __shfl_xor_sync(0xffffffffu, e0, 2);
    e1 += __shfl_xor_sync(0xffffffffu, e1, 1);
    e1 += __shfl_xor_sync(0xffffffffu, e1, 2);
    const int b = bh >> 4, h = bh & 15;
    const int qg0 = q0 + 16*w + g, qg1 = qg0 + 8;
    if ((lane & 3) == 0) {
        ent[(size_t)bh*Nc + qg0] = -e0;
        ent[(size_t)bh*Nc + qg1] = -e1;
    }
    const float gt0 = gate[(size_t)b*Nc + qg0];
    const float gt1 = gate[(size_t)b*Nc + qg1];
    #pragma unroll
    for (int nt = 0; nt < 8; nt++) {
        const int c = h*64 + nt*8 + (lane & 3)*2;
        const size_t a0 = ((size_t)(b*Nc + qg0))*Dc + c;
        const size_t a1 = ((size_t)(b*Nc + qg1))*Dc + c;
        __nv_bfloat162 lo0, lo1;
        __nv_bfloat162 hi0 = split2(oacc[nt][0]*gt0, oacc[nt][1]*gt0, lo0);
        __nv_bfloat162 hi1 = split2(oacc[nt][2]*gt1, oacc[nt][3]*gt1, lo1);
        *(__nv_bfloat162*)&AOh[a0] = hi0;
        *(__nv_bfloat162*)&AOl[a0] = lo0;
        *(__nv_bfloat162*)&AOh[a1] = hi1;
        *(__nv_bfloat162*)&AOl[a1] = lo1;
    }
}

// ---------------------------------------------------------------------------
extern "C" void kernel_launch(void* const* d_in, const int* in_sizes, int n_in,
                              void* d_out, int out_size)
{
    const float* x   = (const float*)d_in[0];
    const float* Wq  = (const float*)d_in[2];
    const float* bq  = (const float*)d_in[3];
    const float* Wk  = (const float*)d_in[4];
    const float* bk  = (const float*)d_in[5];
    const float* Wv  = (const float*)d_in[6];
    const float* bv  = (const float*)d_in[7];
    const float* Wg1 = (const float*)d_in[8];
    const float* bg1 = (const float*)d_in[9];
    const float* Wg2 = (const float*)d_in[10];
    const float* bg2 = (const float*)d_in[11];
    const float* Wo  = (const float*)d_in[12];
    const float* bo  = (const float*)d_in[13];

    float* out = (float*)d_out;                       // [B, N, D]
    float* ent = out + (size_t)Bc*Nc*Dc;              // [B, H, N]

    float *Vp, *G1p, *Gp;
    __nv_bfloat16 *xh, *xl, *qh, *ql, *kh, *kl, *vth, *vtl, *AOh, *AOl, *Wth, *Wtl;
    cudaGetSymbolAddress((void**)&Vp,  g_V);
    cudaGetSymbolAddress((void**)&G1p, g_G1);
    cudaGetSymbolAddress((void**)&Gp,  g_gate);
    cudaGetSymbolAddress((void**)&xh,  g_xh);
    cudaGetSymbolAddress((void**)&xl,  g_xl);
    cudaGetSymbolAddress((void**)&qh,  g_qh);
    cudaGetSymbolAddress((void**)&ql,  g_ql);
    cudaGetSymbolAddress((void**)&kh,  g_kh);
    cudaGetSymbolAddress((void**)&kl,  g_kl);
    cudaGetSymbolAddress((void**)&vth, g_vth);
    cudaGetSymbolAddress((void**)&vtl, g_vtl);
    cudaGetSymbolAddress((void**)&AOh, g_AOh);
    cudaGetSymbolAddress((void**)&AOl, g_AOl);
    cudaGetSymbolAddress((void**)&Wth, g_Wth);
    cudaGetSymbolAddress((void**)&Wtl, g_Wtl);

    const int TCSMEM = 2 * 4 * 128 * KSTR * 2;     // 81920
    cudaFuncSetAttribute(proj_gemm, cudaFuncAttributeMaxDynamicSharedMemorySize, TCSMEM);
    cudaFuncSetAttribute(out_gemm,  cudaFuncAttributeMaxDynamicSharedMemorySize, TCSMEM);
    cudaFuncSetAttribute(attn_k, cudaFuncAttributeMaxDynamicSharedMemorySize, ATT_SMEM_B);

    split_k<<<Mc*Dc/4/256, 256>>>(x, xh, xl, Mc*Dc/4);
    WPtrs wp; wp.w[0] = Wq; wp.w[1] = Wk; wp.w[2] = Wv; wp.w[3] = Wg1; wp.w[4] = Wo;
    tsplit_k<<<dim3(32, 32, 5), 256>>>(wp, Wth, Wtl);

    BPtrs bp; bp.b[0] = bq; bp.b[1] = bk; bp.b[2] = bv; bp.b[3] = bg1;
    proj_gemm<<<dim3(Dc/128, Mc/128, 4), 256, TCSMEM>>>(
        xh, xl, Wth, Wtl, bp, Vp, G1p, qh, ql, kh, kl);

    vt_k<<<dim3(Nc/32, DHc/32, BHc), 256>>>(Vp, vth, vtl);
    gate_k<<<Mc, 256>>>(G1p, Wg2, bg2, Gp);

    attn_k<<<dim3(Nc/128, BHc), 256, ATT_SMEM_B>>>(qh, ql, kh, kl, vth, vtl,
                                                   Gp, AOh, AOl, ent);

    out_gemm<<<dim3(Dc/128, Mc/128), 256, TCSMEM>>>(
        AOh, AOl, Wth + 4*(size_t)Dc*Dc, Wtl + 4*(size_t)Dc*Dc, bo, out);
}

// round 8
// speedup vs baseline: 4.1503x; 1.1493x over previous
#include <cuda_runtime.h>
#include <cuda_bf16.h>
#include <math.h>
#include <stdint.h>

#define Bc 2
#define Nc 1536
#define Dc 1024
#define Hc 16
#define DHc 64
#define Mc (Bc*Nc)
#define BHc (Bc*Hc)
#define KSTR 40     // gemm bf16 smem row stride (80B -> ldmatrix conflict-free)

// attention smem geometry (bf16 element offsets)
#define QS 72       // 64-wide tiles padded: 144B = 9*16B
#define PS 136      // 128-wide tiles padded: 272B = 17*16B
#define OQ_H 0
#define OQ_L 9216
#define OK_H 18432
#define OK_L 27648
#define OV_H 36864
#define OV_L 45568
#define OP_H 54272
#define OP_L 71680
#define ATT_SMEM_B (89088*2)

// ---------------- scratch (allocation-free rule: device globals) ------------
__device__ float g_G1[Mc*Dc];
__device__ float g_gate[Mc];
__device__ __nv_bfloat16 g_xh[Mc*Dc],  g_xl[Mc*Dc];
__device__ __nv_bfloat16 g_qh[BHc*Nc*DHc], g_ql[BHc*Nc*DHc];
__device__ __nv_bfloat16 g_kh[BHc*Nc*DHc], g_kl[BHc*Nc*DHc];
__device__ __nv_bfloat16 g_vth[BHc*DHc*Nc], g_vtl[BHc*DHc*Nc];  // [bh][dh][n]
__device__ __nv_bfloat16 g_AOh[Mc*Dc], g_AOl[Mc*Dc];
__device__ __nv_bfloat16 g_Wth[5][Dc*Dc], g_Wtl[5][Dc*Dc];      // [n][k]

struct WPtrs  { const float* w[5]; };
struct BPtrs  { const float* b[4]; };

// ---------------- PTX helpers ----------------------------------------------
static __device__ __forceinline__ uint32_t smem_u32(const void* p) {
    uint32_t a;
    asm("{ .reg .u64 t; cvta.to.shared.u64 t, %1; cvt.u32.u64 %0, t; }"
        : "=r"(a) : "l"(p));
    return a;
}
#define LDSM4(r0, r1, r2, r3, addr) \
    asm volatile("ldmatrix.sync.aligned.m8n8.x4.shared.b16 {%0,%1,%2,%3}, [%4];" \
                 : "=r"(r0), "=r"(r1), "=r"(r2), "=r"(r3) : "r"(addr))
#define MMA16816(d, a, b0, b1) \
    asm volatile("mma.sync.aligned.m16n8k16.row.col.f32.bf16.bf16.f32 " \
                 "{%0,%1,%2,%3}, {%4,%5,%6,%7}, {%8,%9}, {%0,%1,%2,%3};" \
                 : "+f"((d)[0]), "+f"((d)[1]), "+f"((d)[2]), "+f"((d)[3]) \
                 : "r"((a)[0]), "r"((a)[1]), "r"((a)[2]), "r"((a)[3]), \
                   "r"(b0), "r"(b1))
static __device__ __forceinline__ void cp_async16(uint32_t saddr, const void* gptr) {
    asm volatile("{ .reg .u64 g; cvta.to.global.u64 g, %1; "
                 "cp.async.cg.shared.global [%0], [g], 16; }"
                 :: "r"(saddr), "l"(gptr) : "memory");
}
#define CP_COMMIT() asm volatile("cp.async.commit_group;" ::: "memory")
#define CP_WAIT(n)  asm volatile("cp.async.wait_group %0;" :: "n"(n) : "memory")

static __device__ __forceinline__ __nv_bfloat162 split2(float a, float b,
                                                        __nv_bfloat162& lo) {
    __nv_bfloat16 ha = __float2bfloat16(a), hb = __float2bfloat16(b);
    lo.x = __float2bfloat16(a - __bfloat162float(ha));
    lo.y = __float2bfloat16(b - __bfloat162float(hb));
    __nv_bfloat162 hi; hi.x = ha; hi.y = hb;
    return hi;
}

// ---------------------------------------------------------------------------
// HMMA GEMM mainloop: 128x128 tile, split-bf16 3-term, K-tile 32, double buf.
// ---------------------------------------------------------------------------
static __device__ __forceinline__ void gemm_main(
    const __nv_bfloat16* __restrict__ Ah, const __nv_bfloat16* __restrict__ Al,
    const __nv_bfloat16* __restrict__ Bh, const __nv_bfloat16* __restrict__ Bl,
    int m0, int n0, uint32_t sb, int tid, int wr, int wc, int lane,
    float acc[4][4][4])
{
    const int TILE_B = 128 * KSTR * 2;
    #pragma unroll
    for (int m = 0; m < 4; m++)
        #pragma unroll
        for (int n = 0; n < 4; n++)
            #pragma unroll
            for (int v = 0; v < 4; v++) acc[m][n][v] = 0.f;

    auto issue = [&](int kt, int stg) {
        const int k0 = kt * 32;
        const uint32_t so = sb + stg * 4 * TILE_B;
        #pragma unroll
        for (int j = 0; j < 2; j++) {
            const int cid = tid + j * 256;
            const int r = cid >> 2, c = cid & 3;
            const uint32_t soff = (uint32_t)(r * KSTR + c * 8) * 2;
            const size_t ga = (size_t)(m0 + r) * Dc + k0 + c * 8;
            const size_t gb = (size_t)(n0 + r) * Dc + k0 + c * 8;
            cp_async16(so + soff,              Ah + ga);
            cp_async16(so + TILE_B + soff,     Al + ga);
            cp_async16(so + 2 * TILE_B + soff, Bh + gb);
            cp_async16(so + 3 * TILE_B + soff, Bl + gb);
        }
    };

    issue(0, 0);
    CP_COMMIT();

    for (int kt = 0; kt < 32; kt++) {
        const int stg = kt & 1;
        if (kt + 1 < 32) { issue(kt + 1, stg ^ 1); CP_COMMIT(); CP_WAIT(1); }
        else             { CP_WAIT(0); }
        __syncthreads();

        const uint32_t so  = sb + stg * 4 * TILE_B;
        const uint32_t aAh = so,            aAl = so + TILE_B;
        const uint32_t aBh = so + 2*TILE_B, aBl = so + 3*TILE_B;

        #pragma unroll
        for (int ks = 0; ks < 2; ks++) {
            const int k0 = ks * 16;
            uint32_t bhf[8], blf[8];
            #pragma unroll
            for (int pr = 0; pr < 2; pr++) {
                const int row = wc*32 + pr*16 + ((lane >> 4) & 1)*8 + (lane & 7);
                const int col = k0 + ((lane >> 3) & 1)*8;
                const uint32_t off = (uint32_t)(row * KSTR + col) * 2;
                LDSM4(bhf[pr*4+0], bhf[pr*4+1], bhf[pr*4+2], bhf[pr*4+3], aBh + off);
                LDSM4(blf[pr*4+0], blf[pr*4+1], blf[pr*4+2], blf[pr*4+3], aBl + off);
            }
            #pragma unroll
            for (int m = 0; m < 4; m++) {
                const int row = wr*64 + m*16 + (lane & 7) + ((lane >> 3) & 1)*8;
                const int col = k0 + (lane >> 4)*8;
                const uint32_t off = (uint32_t)(row * KSTR + col) * 2;
                uint32_t ah[4], al[4];
                LDSM4(ah[0], ah[1], ah[2], ah[3], aAh + off);
                LDSM4(al[0], al[1], al[2], al[3], aAl + off);
                #pragma unroll
                for (int n = 0; n < 4; n++) {
                    MMA16816(acc[m][n], ah, bhf[n*2], bhf[n*2+1]);
                    MMA16816(acc[m][n], ah, blf[n*2], blf[n*2+1]);
                    MMA16816(acc[m][n], al, bhf[n*2], bhf[n*2+1]);
                }
            }
        }
        __syncthreads();
    }
}

// ---------------------------------------------------------------------------
// Fused Q/K/V/G1 projection GEMM. blockIdx.z selects weight set + epilogue:
// z=0: Q -> split bf16 scatter, scale 1/8;  z=1: K -> split bf16 scatter;
// z=2: V -> split bf16 TRANSPOSED scatter [bh][dh][n];  z=3: G1 -> GELU fp32.
// ---------------------------------------------------------------------------
__global__ void __launch_bounds__(256, 2)
proj_gemm(const __nv_bfloat16* __restrict__ xh, const __nv_bfloat16* __restrict__ xl,
          const __nv_bfloat16* __restrict__ Wth, const __nv_bfloat16* __restrict__ Wtl,
          BPtrs bp, float* __restrict__ G1out,
          __nv_bfloat16* __restrict__ qh, __nv_bfloat16* __restrict__ ql,
          __nv_bfloat16* __restrict__ kh, __nv_bfloat16* __restrict__ kl,
          __nv_bfloat16* __restrict__ vth, __nv_bfloat16* __restrict__ vtl)
{
    extern __shared__ __nv_bfloat16 sm[];
    const int tid = threadIdx.x, wid = tid >> 5, lane = tid & 31;
    const int m0 = blockIdx.y * 128, n0 = blockIdx.x * 128;
    const int z = blockIdx.z;
    const int wr = wid & 1, wc = wid >> 1;
    const uint32_t sb = smem_u32(sm);
    const float* bias = bp.b[z];

    float acc[4][4][4];
    gemm_main(xh, xl, Wth + (size_t)z*Dc*Dc, Wtl + (size_t)z*Dc*Dc,
              m0, n0, sb, tid, wr, wc, lane, acc);

    const float scale = (z == 0) ? 0.125f : 1.f;
    #pragma unroll
    for (int m = 0; m < 4; m++) {
        #pragma unroll
        for (int n = 0; n < 4; n++) {
            const int c = n0 + wc*32 + n*8 + (lane & 3)*2;
            const float b0 = bias[c], b1 = bias[c + 1];
            #pragma unroll
            for (int hv = 0; hv < 2; hv++) {
                const int r = m0 + wr*64 + m*16 + (lane >> 2) + hv*8;
                float v0 = acc[m][n][hv*2+0] + b0;
                float v1 = acc[m][n][hv*2+1] + b1;
                if (z <= 1) {
                    const int bb = r / Nc, nn = r % Nc;
                    const int h = c >> 6, dh = c & 63;
                    const size_t ad = (((size_t)(bb*Hc + h))*Nc + nn)*DHc + dh;
                    __nv_bfloat162 lo;
                    __nv_bfloat162 hi = split2(v0*scale, v1*scale, lo);
                    if (z == 0) {
                        *(__nv_bfloat162*)&qh[ad] = hi;
                        *(__nv_bfloat162*)&ql[ad] = lo;
                    } else {
                        *(__nv_bfloat162*)&kh[ad] = hi;
                        *(__nv_bfloat162*)&kl[ad] = lo;
                    }
                } else if (z == 2) {
                    // V transposed: [bh][dh][n]
                    const int bb = r / Nc, nn = r % Nc;
                    const int h = c >> 6, dh = c & 63;
                    const size_t ad = (((size_t)(bb*Hc + h))*DHc + dh)*Nc + nn;
                    __nv_bfloat162 lo;
                    __nv_bfloat162 hi = split2(v0, v1, lo);
                    vth[ad]      = hi.x;
                    vth[ad + Nc] = hi.y;
                    vtl[ad]      = lo.x;
                    vtl[ad + Nc] = lo.y;
                } else {
                    float2 o;
                    o.x = 0.5f*v0*(1.f + erff(v0*0.70710678118654752f));
                    o.y = 0.5f*v1*(1.f + erff(v1*0.70710678118654752f));
                    *(float2*)&G1out[(size_t)r*Dc + c] = o;
                }
            }
        }
    }
}

// ---------------------------------------------------------------------------
// Output projection GEMM: out = AO @ Wo^T + bo (fp32 out)
// ---------------------------------------------------------------------------
__global__ void __launch_bounds__(256, 2)
out_gemm(const __nv_bfloat16* __restrict__ Ah, const __nv_bfloat16* __restrict__ Al,
         const __nv_bfloat16* __restrict__ Bh, const __nv_bfloat16* __restrict__ Bl,
         const float* __restrict__ bias, float* __restrict__ C)
{
    extern __shared__ __nv_bfloat16 sm[];
    const int tid = threadIdx.x, wid = tid >> 5, lane = tid & 31;
    const int m0 = blockIdx.y * 128, n0 = blockIdx.x * 128;
    const int wr = wid & 1, wc = wid >> 1;
    const uint32_t sb = smem_u32(sm);

    float acc[4][4][4];
    gemm_main(Ah, Al, Bh, Bl, m0, n0, sb, tid, wr, wc, lane, acc);

    #pragma unroll
    for (int m = 0; m < 4; m++) {
        #pragma unroll
        for (int n = 0; n < 4; n++) {
            const int c = n0 + wc*32 + n*8 + (lane & 3)*2;
            const float b0 = bias[c], b1 = bias[c + 1];
            #pragma unroll
            for (int hv = 0; hv < 2; hv++) {
                const int r = m0 + wr*64 + m*16 + (lane >> 2) + hv*8;
                float2 o = {acc[m][n][hv*2+0] + b0, acc[m][n][hv*2+1] + b1};
                *(float2*)&C[(size_t)r*Dc + c] = o;
            }
        }
    }
}

// ---------------------------------------------------------------------------
// fp32 -> bf16 hi/lo split
// ---------------------------------------------------------------------------
__global__ void split_k(const float* __restrict__ in, __nv_bfloat16* __restrict__ hi,
                        __nv_bfloat16* __restrict__ lo, int n4)
{
    const int i = blockIdx.x * 256 + threadIdx.x;
    if (i >= n4) return;
    float4 v = ((const float4*)in)[i];
    __nv_bfloat162 L0, L1;
    __nv_bfloat162 H0 = split2(v.x, v.y, L0);
    __nv_bfloat162 H1 = split2(v.z, v.w, L1);
    ((__nv_bfloat162*)hi)[i * 2 + 0] = H0;
    ((__nv_bfloat162*)hi)[i * 2 + 1] = H1;
    ((__nv_bfloat162*)lo)[i * 2 + 0] = L0;
    ((__nv_bfloat162*)lo)[i * 2 + 1] = L1;
}

// ---------------------------------------------------------------------------
// Weight transpose + split, all 5 weights in one launch (z selects matrix)
// ---------------------------------------------------------------------------
__global__ void tsplit_k(WPtrs wp, __nv_bfloat16* __restrict__ th,
                         __nv_bfloat16* __restrict__ tl)
{
    __shared__ float t[32][33];
    const int z = blockIdx.z;
    const float* W = wp.w[z];
    th += (size_t)z * Dc * Dc;
    tl += (size_t)z * Dc * Dc;
    const int k0 = blockIdx.y * 32, n0 = blockIdx.x * 32;
    const int lane = threadIdx.x & 31, wr = threadIdx.x >> 5;
    #pragma unroll
    for (int i = 0; i < 4; i++)
        t[wr + i * 8][lane] = W[(size_t)(k0 + wr + i * 8) * Dc + n0 + lane];
    __syncthreads();
    #pragma unroll
    for (int i = 0; i < 4; i++) {
        float v = t[lane][wr + i * 8];
        __nv_bfloat16 h = __float2bfloat16(v);
        th[(size_t)(n0 + wr + i * 8) * Dc + k0 + lane] = h;
        tl[(size_t)(n0 + wr + i * 8) * Dc + k0 + lane] =
            __float2bfloat16(v - __bfloat162float(h));
    }
}

// ---------------------------------------------------------------------------
// Gate: gate[r] = sigmoid( dot(G1[r,:], Wg2) + bg2 )
// ---------------------------------------------------------------------------
__global__ void gate_k(const float* __restrict__ G1, const float* __restrict__ Wg2,
                       const float* __restrict__ bg2, float* __restrict__ gate)
{
    __shared__ float red[256];
    const int r = blockIdx.x;
    float s = 0.f;
    for (int k = threadIdx.x; k < Dc; k += 256)
        s += G1[(size_t)r*Dc + k] * Wg2[k];
    red[threadIdx.x] = s;
    __syncthreads();
    for (int o = 128; o; o >>= 1) {
        if (threadIdx.x < o) red[threadIdx.x] += red[threadIdx.x + o];
        __syncthreads();
    }
    if (threadIdx.x == 0) {
        float z = red[0] + bg2[0];
        gate[r] = 1.f / (1.f + expf(-z));
    }
}

// ---------------------------------------------------------------------------
// Single-pass flash attention (HMMA split-bf16) with closed-form entropy:
// H = m + log(l) - t/l,  t = sum exp(s-m)*s  (online-rescaled like l).
// CTA = (bh, 128-query tile); 8 warps x 16 query rows.
// ---------------------------------------------------------------------------
__device__ __forceinline__ void attn_S(uint32_t sb, int w, int lane, float sacc[16][4])
{
    #pragma unroll
    for (int nt = 0; nt < 16; nt++)
        #pragma unroll
        for (int v = 0; v < 4; v++) sacc[nt][v] = 0.f;
    #pragma unroll
    for (int ks = 0; ks < 4; ks++) {
        const int ar = 16*w + (lane & 7) + ((lane >> 3) & 1)*8;
        const int ac = ks*16 + (lane >> 4)*8;
        uint32_t ah[4], al[4];
        LDSM4(ah[0], ah[1], ah[2], ah[3], sb + (uint32_t)(OQ_H + ar*QS + ac)*2);
        LDSM4(al[0], al[1], al[2], al[3], sb + (uint32_t)(OQ_L + ar*QS + ac)*2);
        #pragma unroll
        for (int np = 0; np < 8; np++) {
            const int br = np*16 + ((lane >> 4) & 1)*8 + (lane & 7);
            const int bc = ks*16 + ((lane >> 3) & 1)*8;
            uint32_t bh4[4], bl4[4];
            LDSM4(bh4[0], bh4[1], bh4[2], bh4[3], sb + (uint32_t)(OK_H + br*QS + bc)*2);
            LDSM4(bl4[0], bl4[1], bl4[2], bl4[3], sb + (uint32_t)(OK_L + br*QS + bc)*2);
            MMA16816(sacc[2*np],   ah, bh4[0], bh4[1]);
            MMA16816(sacc[2*np],   ah, bl4[0], bl4[1]);
            MMA16816(sacc[2*np],   al, bh4[0], bh4[1]);
            MMA16816(sacc[2*np+1], ah, bh4[2], bh4[3]);
            MMA16816(sacc[2*np+1], ah, bl4[2], bl4[3]);
            MMA16816(sacc[2*np+1], al, bh4[2], bh4[3]);
        }
    }
}

__global__ void __launch_bounds__(256)
attn_k(const __nv_bfloat16* __restrict__ Qh, const __nv_bfloat16* __restrict__ Ql,
       const __nv_bfloat16* __restrict__ Kh, const __nv_bfloat16* __restrict__ Kl,
       const __nv_bfloat16* __restrict__ Vth, const __nv_bfloat16* __restrict__ Vtl,
       const float* __restrict__ gate, __nv_bfloat16* __restrict__ AOh,
       __nv_bfloat16* __restrict__ AOl, float* __restrict__ ent)
{
    extern __shared__ __nv_bfloat16 sm[];
    const int tid = threadIdx.x, w = tid >> 5, lane = tid & 31;
    const int qt = (gridDim.x - 1) - blockIdx.x;   // heavy tiles first
    const int bh = blockIdx.y;
    const int q0 = qt * 128;
    const int ntk = qt + 1;
    const uint32_t sb = smem_u32(sm);

    {
        const __nv_bfloat16* qh = Qh + ((size_t)bh*Nc + q0)*DHc;
        const __nv_bfloat16* ql = Ql + ((size_t)bh*Nc + q0)*DHc;
        #pragma unroll
        for (int i = tid; i < 1024; i += 256) {
            const int r = i >> 3, c = i & 7;
            *(uint4*)&sm[OQ_H + r*QS + c*8] = *(const uint4*)&qh[r*64 + c*8];
            *(uint4*)&sm[OQ_L + r*QS + c*8] = *(const uint4*)&ql[r*64 + c*8];
        }
    }

    const int g = lane >> 2;
    float m0 = -1e30f, m1 = -1e30f, l0 = 0.f, l1 = 0.f, t0 = 0.f, t1 = 0.f;
    float sacc[16][4];
    float oacc[8][4];
    #pragma unroll
    for (int nt = 0; nt < 8; nt++)
        #pragma unroll
        for (int v = 0; v < 4; v++) oacc[nt][v] = 0.f;

    for (int kt = 0; kt < ntk; kt++) {
        __syncthreads();
        {
            const __nv_bfloat16* kh = Kh + ((size_t)bh*Nc + kt*128)*DHc;
            const __nv_bfloat16* kl = Kl + ((size_t)bh*Nc + kt*128)*DHc;
            #pragma unroll
            for (int i = tid; i < 1024; i += 256) {
                const int r = i >> 3, c = i & 7;
                *(uint4*)&sm[OK_H + r*QS + c*8] = *(const uint4*)&kh[r*64 + c*8];
                *(uint4*)&sm[OK_L + r*QS + c*8] = *(const uint4*)&kl[r*64 + c*8];
            }
            #pragma unroll
            for (int i = tid; i < 1024; i += 256) {
                const int r = i >> 4, c = i & 15;
                const size_t ad = ((size_t)bh*DHc + r)*Nc + kt*128 + c*8;
                *(uint4*)&sm[OV_H + r*PS + c*8] = *(const uint4*)&Vth[ad];
                *(uint4*)&sm[OV_L + r*PS + c*8] = *(const uint4*)&Vtl[ad];
            }
        }
        __syncthreads();
        attn_S(sb, w, lane, sacc);
        if (kt == qt) {
            #pragma unroll
            for (int nt = 0; nt < 16; nt++) {
                const int c0 = nt*8 + (lane & 3)*2;
                if (c0     > 16*w + g)     sacc[nt][0] = -1e30f;
                if (c0 + 1 > 16*w + g)     sacc[nt][1] = -1e30f;
                if (c0     > 16*w + g + 8) sacc[nt][2] = -1e30f;
                if (c0 + 1 > 16*w + g + 8) sacc[nt][3] = -1e30f;
            }
        }
        // tile row max
        float mt0 = -1e30f, mt1 = -1e30f;
        #pragma unroll
        for (int nt = 0; nt < 16; nt++) {
            mt0 = fmaxf(mt0, fmaxf(sacc[nt][0], sacc[nt][1]));
            mt1 = fmaxf(mt1, fmaxf(sacc[nt][2], sacc[nt][3]));
        }
        mt0 = fmaxf(mt0, __shfl_xor_sync(0xffffffffu, mt0, 1));
        mt0 = fmaxf(mt0, __shfl_xor_sync(0xffffffffu, mt0, 2));
        mt1 = fmaxf(mt1, __shfl_xor_sync(0xffffffffu, mt1, 1));
        mt1 = fmaxf(mt1, __shfl_xor_sync(0xffffffffu, mt1, 2));
        const float mn0 = fmaxf(m0, mt0), mn1 = fmaxf(m1, mt1);
        const float sc0 = __expf(m0 - mn0), sc1 = __expf(m1 - mn1);

        // p (unnormalized), l/t partials, store p to smem split-bf16
        const int pr0 = 16*w + g, pr1 = pr0 + 8;
        float s0 = 0.f, s1 = 0.f, u0 = 0.f, u1 = 0.f;
        #pragma unroll
        for (int nt = 0; nt < 16; nt++) {
            const int c0 = nt*8 + (lane & 3)*2;
            const float p00 = __expf(sacc[nt][0]-mn0);
            const float p01 = __expf(sacc[nt][1]-mn0);
            const float p10 = __expf(sacc[nt][2]-mn1);
            const float p11 = __expf(sacc[nt][3]-mn1);
            s0 += p00 + p01;
            s1 += p10 + p11;
            u0 += p00*sacc[nt][0] + p01*sacc[nt][1];
            u1 += p10*sacc[nt][2] + p11*sacc[nt][3];
            __nv_bfloat162 lo0, lo1;
            __nv_bfloat162 hi0 = split2(p00, p01, lo0);
            __nv_bfloat162 hi1 = split2(p10, p11, lo1);
            *(__nv_bfloat162*)&sm[OP_H + pr0*PS + c0] = hi0;
            *(__nv_bfloat162*)&sm[OP_L + pr0*PS + c0] = lo0;
            *(__nv_bfloat162*)&sm[OP_H + pr1*PS + c0] = hi1;
            *(__nv_bfloat162*)&sm[OP_L + pr1*PS + c0] = lo1;
        }
        s0 += __shfl_xor_sync(0xffffffffu, s0, 1);
        s0 += __shfl_xor_sync(0xffffffffu, s0, 2);
        s1 += __shfl_xor_sync(0xffffffffu, s1, 1);
        s1 += __shfl_xor_sync(0xffffffffu, s1, 2);
        u0 += __shfl_xor_sync(0xffffffffu, u0, 1);
        u0 += __shfl_xor_sync(0xffffffffu, u0, 2);
        u1 += __shfl_xor_sync(0xffffffffu, u1, 1);
        u1 += __shfl_xor_sync(0xffffffffu, u1, 2);
        l0 = l0*sc0 + s0;  t0 = t0*sc0 + u0;  m0 = mn0;
        l1 = l1*sc1 + s1;  t1 = t1*sc1 + u1;  m1 = mn1;

        // rescale running O
        #pragma unroll
        for (int nt = 0; nt < 8; nt++) {
            oacc[nt][0] *= sc0; oacc[nt][1] *= sc0;
            oacc[nt][2] *= sc1; oacc[nt][3] *= sc1;
        }
        __syncthreads();

        // O += P @ V^T-tiles
        #pragma unroll
        for (int ks = 0; ks < 8; ks++) {
            const int ar = 16*w + (lane & 7) + ((lane >> 3) & 1)*8;
            const int ac = ks*16 + (lane >> 4)*8;
            uint32_t ah[4], al[4];
            LDSM4(ah[0], ah[1], ah[2], ah[3], sb + (uint32_t)(OP_H + ar*PS + ac)*2);
            LDSM4(al[0], al[1], al[2], al[3], sb + (uint32_t)(OP_L + ar*PS + ac)*2);
            #pragma unroll
            for (int np = 0; np < 4; np++) {
                const int br = np*16 + ((lane >> 4) & 1)*8 + (lane & 7);
                const int bc = ks*16 + ((lane >> 3) & 1)*8;
                uint32_t bh4[4], bl4[4];
                LDSM4(bh4[0], bh4[1], bh4[2], bh4[3], sb + (uint32_t)(OV_H + br*PS + bc)*2);
                LDSM4(bl4[0], bl4[1], bl4[2], bl4[3], sb + (uint32_t)(OV_L + br*PS + bc)*2);
                MMA16816(oacc[2*np],   ah, bh4[0], bh4[1]);
                MMA16816(oacc[2*np],   ah, bl4[0], bl4[1]);
                MMA16816(oacc[2*np],   al, bh4[0], bh4[1]);
                MMA16816(oacc[2*np+1], ah, bh4[2], bh4[3]);
                MMA16816(oacc[2*np+1], ah, bl4[2], bl4[3]);
                MMA16816(oacc[2*np+1], al, bh4[2], bh4[3]);
            }
        }
    }

    // ---------------- epilogue ----------------
    const float il0 = 1.f / l0, il1 = 1.f / l1;
    const int b = bh >> 4, h = bh & 15;
    const int qg0 = q0 + 16*w + g, qg1 = qg0 + 8;
    if ((lane & 3) == 0) {
        ent[(size_t)bh*Nc + qg0] = m0 + __logf(l0) - t0*il0;
        ent[(size_t)bh*Nc + qg1] = m1 + __logf(l1) - t1*il1;
    }
    const float gt0 = gate[(size_t)b*Nc + qg0] * il0;
    const float gt1 = gate[(size_t)b*Nc + qg1] * il1;
    #pragma unroll
    for (int nt = 0; nt < 8; nt++) {
        const int c = h*64 + nt*8 + (lane & 3)*2;
        const size_t a0 = ((size_t)(b*Nc + qg0))*Dc + c;
        const size_t a1 = ((size_t)(b*Nc + qg1))*Dc + c;
        __nv_bfloat162 lo0, lo1;
        __nv_bfloat162 hi0 = split2(oacc[nt][0]*gt0, oacc[nt][1]*gt0, lo0);
        __nv_bfloat162 hi1 = split2(oacc[nt][2]*gt1, oacc[nt][3]*gt1, lo1);
        *(__nv_bfloat162*)&AOh[a0] = hi0;
        *(__nv_bfloat162*)&AOl[a0] = lo0;
        *(__nv_bfloat162*)&AOh[a1] = hi1;
        *(__nv_bfloat162*)&AOl[a1] = lo1;
    }
}

// ---------------------------------------------------------------------------
extern "C" void kernel_launch(void* const* d_in, const int* in_sizes, int n_in,
                              void* d_out, int out_size)
{
    const float* x   = (const float*)d_in[0];
    const float* Wq  = (const float*)d_in[2];
    const float* bq  = (const float*)d_in[3];
    const float* Wk  = (const float*)d_in[4];
    const float* bk  = (const float*)d_in[5];
    const float* Wv  = (const float*)d_in[6];
    const float* bv  = (const float*)d_in[7];
    const float* Wg1 = (const float*)d_in[8];
    const float* bg1 = (const float*)d_in[9];
    const float* Wg2 = (const float*)d_in[10];
    const float* bg2 = (const float*)d_in[11];
    const float* Wo  = (const float*)d_in[12];
    const float* bo  = (const float*)d_in[13];

    float* out = (float*)d_out;                       // [B, N, D]
    float* ent = out + (size_t)Bc*Nc*Dc;              // [B, H, N]

    float *G1p, *Gp;
    __nv_bfloat16 *xh, *xl, *qh, *ql, *kh, *kl, *vth, *vtl, *AOh, *AOl, *Wth, *Wtl;
    cudaGetSymbolAddress((void**)&G1p, g_G1);
    cudaGetSymbolAddress((void**)&Gp,  g_gate);
    cudaGetSymbolAddress((void**)&xh,  g_xh);
    cudaGetSymbolAddress((void**)&xl,  g_xl);
    cudaGetSymbolAddress((void**)&qh,  g_qh);
    cudaGetSymbolAddress((void**)&ql,  g_ql);
    cudaGetSymbolAddress((void**)&kh,  g_kh);
    cudaGetSymbolAddress((void**)&kl,  g_kl);
    cudaGetSymbolAddress((void**)&vth, g_vth);
    cudaGetSymbolAddress((void**)&vtl, g_vtl);
    cudaGetSymbolAddress((void**)&AOh, g_AOh);
    cudaGetSymbolAddress((void**)&AOl, g_AOl);
    cudaGetSymbolAddress((void**)&Wth, g_Wth);
    cudaGetSymbolAddress((void**)&Wtl, g_Wtl);

    const int TCSMEM = 2 * 4 * 128 * KSTR * 2;     // 81920
    cudaFuncSetAttribute(proj_gemm, cudaFuncAttributeMaxDynamicSharedMemorySize, TCSMEM);
    cudaFuncSetAttribute(out_gemm,  cudaFuncAttributeMaxDynamicSharedMemorySize, TCSMEM);
    cudaFuncSetAttribute(attn_k, cudaFuncAttributeMaxDynamicSharedMemorySize, ATT_SMEM_B);

    split_k<<<Mc*Dc/4/256, 256>>>(x, xh, xl, Mc*Dc/4);
    WPtrs wp; wp.w[0] = Wq; wp.w[1] = Wk; wp.w[2] = Wv; wp.w[3] = Wg1; wp.w[4] = Wo;
    tsplit_k<<<dim3(32, 32, 5), 256>>>(wp, Wth, Wtl);

    BPtrs bp; bp.b[0] = bq; bp.b[1] = bk; bp.b[2] = bv; bp.b[3] = bg1;
    proj_gemm<<<dim3(Dc/128, Mc/128, 4), 256, TCSMEM>>>(
        xh, xl, Wth, Wtl, bp, G1p, qh, ql, kh, kl, vth, vtl);

    gate_k<<<Mc, 256>>>(G1p, Wg2, bg2, Gp);

    attn_k<<<dim3(Nc/128, BHc), 256, ATT_SMEM_B>>>(qh, ql, kh, kl, vth, vtl,
                                                   Gp, AOh, AOl, ent);

    out_gemm<<<dim3(Dc/128, Mc/128), 256, TCSMEM>>>(
        AOh, AOl, Wth + 4*(size_t)Dc*Dc, Wtl + 4*(size_t)Dc*Dc, bo, out);
}

// round 9
// speedup vs baseline: 4.2068x; 1.0136x over previous
#include <cuda_runtime.h>
#include <cuda_bf16.h>
#include <math.h>
#include <stdint.h>

#define Bc 2
#define Nc 1536
#define Dc 1024
#define Hc 16
#define DHc 64
#define Mc (Bc*Nc)
#define BHc (Bc*Hc)
#define KSTR 40     // gemm bf16 smem row stride (80B -> ldmatrix conflict-free)

// attention smem geometry (bf16 element offsets)
#define QS 72       // 64-wide tiles padded: 144B = 9*16B
#define PS 136      // 128-wide tiles padded: 272B = 17*16B
#define OQ_H 0
#define OQ_L 9216
#define OK_H 18432
#define OK_L 27648
#define OV_H 36864
#define OV_L 45568
#define OP_H 54272
#define OP_L 71680
#define ATT_SMEM_B (89088*2)

// ---------------- scratch (allocation-free rule: device globals) ------------
__device__ float g_gacc[Mc];                          // gate logits (atomic acc)
__device__ __nv_bfloat16 g_xh[Mc*Dc],  g_xl[Mc*Dc];
__device__ __nv_bfloat16 g_qh[BHc*Nc*DHc], g_ql[BHc*Nc*DHc];
__device__ __nv_bfloat16 g_kh[BHc*Nc*DHc], g_kl[BHc*Nc*DHc];
__device__ __nv_bfloat16 g_vth[BHc*DHc*Nc], g_vtl[BHc*DHc*Nc];  // [bh][dh][n]
__device__ __nv_bfloat16 g_AOh[Mc*Dc], g_AOl[Mc*Dc];
__device__ __nv_bfloat16 g_Wth[5][Dc*Dc], g_Wtl[5][Dc*Dc];      // [n][k]

struct WPtrs  { const float* w[5]; };
struct BPtrs  { const float* b[4]; };

// ---------------- PTX helpers ----------------------------------------------
static __device__ __forceinline__ uint32_t smem_u32(const void* p) {
    uint32_t a;
    asm("{ .reg .u64 t; cvta.to.shared.u64 t, %1; cvt.u32.u64 %0, t; }"
        : "=r"(a) : "l"(p));
    return a;
}
#define LDSM4(r0, r1, r2, r3, addr) \
    asm volatile("ldmatrix.sync.aligned.m8n8.x4.shared.b16 {%0,%1,%2,%3}, [%4];" \
                 : "=r"(r0), "=r"(r1), "=r"(r2), "=r"(r3) : "r"(addr))
#define MMA16816(d, a, b0, b1) \
    asm volatile("mma.sync.aligned.m16n8k16.row.col.f32.bf16.bf16.f32 " \
                 "{%0,%1,%2,%3}, {%4,%5,%6,%7}, {%8,%9}, {%0,%1,%2,%3};" \
                 : "+f"((d)[0]), "+f"((d)[1]), "+f"((d)[2]), "+f"((d)[3]) \
                 : "r"((a)[0]), "r"((a)[1]), "r"((a)[2]), "r"((a)[3]), \
                   "r"(b0), "r"(b1))
static __device__ __forceinline__ void cp_async16(uint32_t saddr, const void* gptr) {
    asm volatile("{ .reg .u64 g; cvta.to.global.u64 g, %1; "
                 "cp.async.cg.shared.global [%0], [g], 16; }"
                 :: "r"(saddr), "l"(gptr) : "memory");
}
#define CP_COMMIT() asm volatile("cp.async.commit_group;" ::: "memory")
#define CP_WAIT(n)  asm volatile("cp.async.wait_group %0;" :: "n"(n) : "memory")

static __device__ __forceinline__ __nv_bfloat162 split2(float a, float b,
                                                        __nv_bfloat162& lo) {
    __nv_bfloat16 ha = __float2bfloat16(a), hb = __float2bfloat16(b);
    lo.x = __float2bfloat16(a - __bfloat162float(ha));
    lo.y = __float2bfloat16(b - __bfloat162float(hb));
    __nv_bfloat162 hi; hi.x = ha; hi.y = hb;
    return hi;
}

// ---------------------------------------------------------------------------
// HMMA GEMM mainloop: 128x128 tile, split-bf16 3-term, K-tile 32, double buf.
// MMA chains interleaved over n (dependency distance 4).
// ---------------------------------------------------------------------------
static __device__ __forceinline__ void gemm_main(
    const __nv_bfloat16* __restrict__ Ah, const __nv_bfloat16* __restrict__ Al,
    const __nv_bfloat16* __restrict__ Bh, const __nv_bfloat16* __restrict__ Bl,
    int m0, int n0, uint32_t sb, int tid, int wr, int wc, int lane,
    float acc[4][4][4])
{
    const int TILE_B = 128 * KSTR * 2;
    #pragma unroll
    for (int m = 0; m < 4; m++)
        #pragma unroll
        for (int n = 0; n < 4; n++)
            #pragma unroll
            for (int v = 0; v < 4; v++) acc[m][n][v] = 0.f;

    auto issue = [&](int kt, int stg) {
        const int k0 = kt * 32;
        const uint32_t so = sb + stg * 4 * TILE_B;
        #pragma unroll
        for (int j = 0; j < 2; j++) {
            const int cid = tid + j * 256;
            const int r = cid >> 2, c = cid & 3;
            const uint32_t soff = (uint32_t)(r * KSTR + c * 8) * 2;
            const size_t ga = (size_t)(m0 + r) * Dc + k0 + c * 8;
            const size_t gb = (size_t)(n0 + r) * Dc + k0 + c * 8;
            cp_async16(so + soff,              Ah + ga);
            cp_async16(so + TILE_B + soff,     Al + ga);
            cp_async16(so + 2 * TILE_B + soff, Bh + gb);
            cp_async16(so + 3 * TILE_B + soff, Bl + gb);
        }
    };

    issue(0, 0);
    CP_COMMIT();

    for (int kt = 0; kt < 32; kt++) {
        const int stg = kt & 1;
        if (kt + 1 < 32) { issue(kt + 1, stg ^ 1); CP_COMMIT(); CP_WAIT(1); }
        else             { CP_WAIT(0); }
        __syncthreads();

        const uint32_t so  = sb + stg * 4 * TILE_B;
        const uint32_t aAh = so,            aAl = so + TILE_B;
        const uint32_t aBh = so + 2*TILE_B, aBl = so + 3*TILE_B;

        #pragma unroll
        for (int ks = 0; ks < 2; ks++) {
            const int k0 = ks * 16;
            uint32_t bhf[8], blf[8];
            #pragma unroll
            for (int pr = 0; pr < 2; pr++) {
                const int row = wc*32 + pr*16 + ((lane >> 4) & 1)*8 + (lane & 7);
                const int col = k0 + ((lane >> 3) & 1)*8;
                const uint32_t off = (uint32_t)(row * KSTR + col) * 2;
                LDSM4(bhf[pr*4+0], bhf[pr*4+1], bhf[pr*4+2], bhf[pr*4+3], aBh + off);
                LDSM4(blf[pr*4+0], blf[pr*4+1], blf[pr*4+2], blf[pr*4+3], aBl + off);
            }
            #pragma unroll
            for (int m = 0; m < 4; m++) {
                const int row = wr*64 + m*16 + (lane & 7) + ((lane >> 3) & 1)*8;
                const int col = k0 + (lane >> 4)*8;
                const uint32_t off = (uint32_t)(row * KSTR + col) * 2;
                uint32_t ah[4], al[4];
                LDSM4(ah[0], ah[1], ah[2], ah[3], aAh + off);
                LDSM4(al[0], al[1], al[2], al[3], aAl + off);
                // term-major ordering: each acc revisited at distance 4
                #pragma unroll
                for (int n = 0; n < 4; n++)
                    MMA16816(acc[m][n], ah, bhf[n*2], bhf[n*2+1]);
                #pragma unroll
                for (int n = 0; n < 4; n++)
                    MMA16816(acc[m][n], ah, blf[n*2], blf[n*2+1]);
                #pragma unroll
                for (int n = 0; n < 4; n++)
                    MMA16816(acc[m][n], al, bhf[n*2], bhf[n*2+1]);
            }
        }
        __syncthreads();
    }
}

// ---------------------------------------------------------------------------
// Fused Q/K/V/G1 projection GEMM. blockIdx.z selects weight set + epilogue:
// z=0: Q -> split bf16 scatter, scale 1/8;  z=1: K -> split bf16 scatter;
// z=2: V -> split bf16 TRANSPOSED scatter [bh][dh][n];
// z=3: gate hidden -> GELU, dot with Wg2 accumulated via atomics (no G1 store).
// ---------------------------------------------------------------------------
__global__ void __launch_bounds__(256, 2)
proj_gemm(const __nv_bfloat16* __restrict__ xh, const __nv_bfloat16* __restrict__ xl,
          const __nv_bfloat16* __restrict__ Wth, const __nv_bfloat16* __restrict__ Wtl,
          BPtrs bp, const float* __restrict__ Wg2, float* __restrict__ gacc,
          __nv_bfloat16* __restrict__ qh, __nv_bfloat16* __restrict__ ql,
          __nv_bfloat16* __restrict__ kh, __nv_bfloat16* __restrict__ kl,
          __nv_bfloat16* __restrict__ vth, __nv_bfloat16* __restrict__ vtl)
{
    extern __shared__ __nv_bfloat16 sm[];
    const int tid = threadIdx.x, wid = tid >> 5, lane = tid & 31;
    const int m0 = blockIdx.y * 128, n0 = blockIdx.x * 128;
    const int z = blockIdx.z;
    const int wr = wid & 1, wc = wid >> 1;
    const uint32_t sb = smem_u32(sm);
    const float* bias = bp.b[z];

    float acc[4][4][4];
    gemm_main(xh, xl, Wth + (size_t)z*Dc*Dc, Wtl + (size_t)z*Dc*Dc,
              m0, n0, sb, tid, wr, wc, lane, acc);

    const float scale = (z == 0) ? 0.125f : 1.f;
    float part[4][2];
    #pragma unroll
    for (int m = 0; m < 4; m++) { part[m][0] = 0.f; part[m][1] = 0.f; }

    #pragma unroll
    for (int m = 0; m < 4; m++) {
        #pragma unroll
        for (int n = 0; n < 4; n++) {
            const int c = n0 + wc*32 + n*8 + (lane & 3)*2;
            const float b0 = bias[c], b1 = bias[c + 1];
            #pragma unroll
            for (int hv = 0; hv < 2; hv++) {
                const int r = m0 + wr*64 + m*16 + (lane >> 2) + hv*8;
                float v0 = acc[m][n][hv*2+0] + b0;
                float v1 = acc[m][n][hv*2+1] + b1;
                if (z <= 1) {
                    const int bb = r / Nc, nn = r % Nc;
                    const int h = c >> 6, dh = c & 63;
                    const size_t ad = (((size_t)(bb*Hc + h))*Nc + nn)*DHc + dh;
                    __nv_bfloat162 lo;
                    __nv_bfloat162 hi = split2(v0*scale, v1*scale, lo);
                    if (z == 0) {
                        *(__nv_bfloat162*)&qh[ad] = hi;
                        *(__nv_bfloat162*)&ql[ad] = lo;
                    } else {
                        *(__nv_bfloat162*)&kh[ad] = hi;
                        *(__nv_bfloat162*)&kl[ad] = lo;
                    }
                } else if (z == 2) {
                    // V transposed: [bh][dh][n]
                    const int bb = r / Nc, nn = r % Nc;
                    const int h = c >> 6, dh = c & 63;
                    const size_t ad = (((size_t)(bb*Hc + h))*DHc + dh)*Nc + nn;
                    __nv_bfloat162 lo;
                    __nv_bfloat162 hi = split2(v0, v1, lo);
                    vth[ad]      = hi.x;
                    vth[ad + Nc] = hi.y;
                    vtl[ad]      = lo.x;
                    vtl[ad + Nc] = lo.y;
                } else {
                    const float g0 = 0.5f*v0*(1.f + erff(v0*0.70710678118654752f));
                    const float g1 = 0.5f*v1*(1.f + erff(v1*0.70710678118654752f));
                    part[m][hv] += g0*Wg2[c] + g1*Wg2[c+1];
                }
            }
        }
    }

    if (z == 3) {
        #pragma unroll
        for (int m = 0; m < 4; m++)
            #pragma unroll
            for (int hv = 0; hv < 2; hv++) {
                float p = part[m][hv];
                p += __shfl_xor_sync(0xffffffffu, p, 1);
                p += __shfl_xor_sync(0xffffffffu, p, 2);
                if ((lane & 3) == 0) {
                    const int r = m0 + wr*64 + m*16 + (lane >> 2) + hv*8;
                    atomicAdd(&gacc[r], p);
                }
            }
    }
}

// ---------------------------------------------------------------------------
// Output projection GEMM: out = AO @ Wo^T + bo (fp32 out)
// ---------------------------------------------------------------------------
__global__ void __launch_bounds__(256, 2)
out_gemm(const __nv_bfloat16* __restrict__ Ah, const __nv_bfloat16* __restrict__ Al,
         const __nv_bfloat16* __restrict__ Bh, const __nv_bfloat16* __restrict__ Bl,
         const float* __restrict__ bias, float* __restrict__ C)
{
    extern __shared__ __nv_bfloat16 sm[];
    const int tid = threadIdx.x, wid = tid >> 5, lane = tid & 31;
    const int m0 = blockIdx.y * 128, n0 = blockIdx.x * 128;
    const int wr = wid & 1, wc = wid >> 1;
    const uint32_t sb = smem_u32(sm);

    float acc[4][4][4];
    gemm_main(Ah, Al, Bh, Bl, m0, n0, sb, tid, wr, wc, lane, acc);

    #pragma unroll
    for (int m = 0; m < 4; m++) {
        #pragma unroll
        for (int n = 0; n < 4; n++) {
            const int c = n0 + wc*32 + n*8 + (lane & 3)*2;
            const float b0 = bias[c], b1 = bias[c + 1];
            #pragma unroll
            for (int hv = 0; hv < 2; hv++) {
                const int r = m0 + wr*64 + m*16 + (lane >> 2) + hv*8;
                float2 o = {acc[m][n][hv*2+0] + b0, acc[m][n][hv*2+1] + b1};
                *(float2*)&C[(size_t)r*Dc + c] = o;
            }
        }
    }
}

// ---------------------------------------------------------------------------
// zero the gate accumulator (graph-replay safe)
// ---------------------------------------------------------------------------
__global__ void zg_k(float* __restrict__ gacc)
{
    gacc[blockIdx.x * 256 + threadIdx.x] = 0.f;
}

// ---------------------------------------------------------------------------
// fp32 -> bf16 hi/lo split
// ---------------------------------------------------------------------------
__global__ void split_k(const float* __restrict__ in, __nv_bfloat16* __restrict__ hi,
                        __nv_bfloat16* __restrict__ lo, int n4)
{
    const int i = blockIdx.x * 256 + threadIdx.x;
    if (i >= n4) return;
    float4 v = ((const float4*)in)[i];
    __nv_bfloat162 L0, L1;
    __nv_bfloat162 H0 = split2(v.x, v.y, L0);
    __nv_bfloat162 H1 = split2(v.z, v.w, L1);
    ((__nv_bfloat162*)hi)[i * 2 + 0] = H0;
    ((__nv_bfloat162*)hi)[i * 2 + 1] = H1;
    ((__nv_bfloat162*)lo)[i * 2 + 0] = L0;
    ((__nv_bfloat162*)lo)[i * 2 + 1] = L1;
}

// ---------------------------------------------------------------------------
// Weight transpose + split, all 5 weights in one launch (z selects matrix)
// ---------------------------------------------------------------------------
__global__ void tsplit_k(WPtrs wp, __nv_bfloat16* __restrict__ th,
                         __nv_bfloat16* __restrict__ tl)
{
    __shared__ float t[32][33];
    const int z = blockIdx.z;
    const float* W = wp.w[z];
    th += (size_t)z * Dc * Dc;
    tl += (size_t)z * Dc * Dc;
    const int k0 = blockIdx.y * 32, n0 = blockIdx.x * 32;
    const int lane = threadIdx.x & 31, wr = threadIdx.x >> 5;
    #pragma unroll
    for (int i = 0; i < 4; i++)
        t[wr + i * 8][lane] = W[(size_t)(k0 + wr + i * 8) * Dc + n0 + lane];
    __syncthreads();
    #pragma unroll
    for (int i = 0; i < 4; i++) {
        float v = t[lane][wr + i * 8];
        __nv_bfloat16 h = __float2bfloat16(v);
        th[(size_t)(n0 + wr + i * 8) * Dc + k0 + lane] = h;
        tl[(size_t)(n0 + wr + i * 8) * Dc + k0 + lane] =
            __float2bfloat16(v - __bfloat162float(h));
    }
}

// ---------------------------------------------------------------------------
// Single-pass flash attention (HMMA split-bf16) with closed-form entropy:
// H = m + log(l) - t/l,  t = sum exp(s-m)*s  (online-rescaled like l).
// CTA = (bh, 128-query tile); 8 warps x 16 query rows. Gate sigmoid fused.
// ---------------------------------------------------------------------------
__device__ __forceinline__ void attn_S(uint32_t sb, int w, int lane, float sacc[16][4])
{
    #pragma unroll
    for (int nt = 0; nt < 16; nt++)
        #pragma unroll
        for (int v = 0; v < 4; v++) sacc[nt][v] = 0.f;
    #pragma unroll
    for (int ks = 0; ks < 4; ks++) {
        const int ar = 16*w + (lane & 7) + ((lane >> 3) & 1)*8;
        const int ac = ks*16 + (lane >> 4)*8;
        uint32_t ah[4], al[4];
        LDSM4(ah[0], ah[1], ah[2], ah[3], sb + (uint32_t)(OQ_H + ar*QS + ac)*2);
        LDSM4(al[0], al[1], al[2], al[3], sb + (uint32_t)(OQ_L + ar*QS + ac)*2);
        #pragma unroll
        for (int pp = 0; pp < 4; pp++) {           // np pairs -> distance-4 chains
            const int np0 = 2*pp, np1 = 2*pp + 1;
            const int bc = ks*16 + ((lane >> 3) & 1)*8;
            const int brA = np0*16 + ((lane >> 4) & 1)*8 + (lane & 7);
            const int brB = np1*16 + ((lane >> 4) & 1)*8 + (lane & 7);
            uint32_t bAh[4], bAl[4], bBh[4], bBl[4];
            LDSM4(bAh[0], bAh[1], bAh[2], bAh[3], sb + (uint32_t)(OK_H + brA*QS + bc)*2);
            LDSM4(bAl[0], bAl[1], bAl[2], bAl[3], sb + (uint32_t)(OK_L + brA*QS + bc)*2);
            LDSM4(bBh[0], bBh[1], bBh[2], bBh[3], sb + (uint32_t)(OK_H + brB*QS + bc)*2);
            LDSM4(bBl[0], bBl[1], bBl[2], bBl[3], sb + (uint32_t)(OK_L + brB*QS + bc)*2);
            MMA16816(sacc[2*np0],   ah, bAh[0], bAh[1]);
            MMA16816(sacc[2*np0+1], ah, bAh[2], bAh[3]);
            MMA16816(sacc[2*np1],   ah, bBh[0], bBh[1]);
            MMA16816(sacc[2*np1+1], ah, bBh[2], bBh[3]);
            MMA16816(sacc[2*np0],   ah, bAl[0], bAl[1]);
            MMA16816(sacc[2*np0+1], ah, bAl[2], bAl[3]);
            MMA16816(sacc[2*np1],   ah, bBl[0], bBl[1]);
            MMA16816(sacc[2*np1+1], ah, bBl[2], bBl[3]);
            MMA16816(sacc[2*np0],   al, bAh[0], bAh[1]);
            MMA16816(sacc[2*np0+1], al, bAh[2], bAh[3]);
            MMA16816(sacc[2*np1],   al, bBh[0], bBh[1]);
            MMA16816(sacc[2*np1+1], al, bBh[2], bBh[3]);
        }
    }
}

__global__ void __launch_bounds__(256)
attn_k(const __nv_bfloat16* __restrict__ Qh, const __nv_bfloat16* __restrict__ Ql,
       const __nv_bfloat16* __restrict__ Kh, const __nv_bfloat16* __restrict__ Kl,
       const __nv_bfloat16* __restrict__ Vth, const __nv_bfloat16* __restrict__ Vtl,
       const float* __restrict__ gacc, const float* __restrict__ bg2,
       __nv_bfloat16* __restrict__ AOh, __nv_bfloat16* __restrict__ AOl,
       float* __restrict__ ent)
{
    extern __shared__ __nv_bfloat16 sm[];
    const int tid = threadIdx.x, w = tid >> 5, lane = tid & 31;
    const int qt = (gridDim.x - 1) - blockIdx.x;   // heavy tiles first
    const int bh = blockIdx.y;
    const int q0 = qt * 128;
    const int ntk = qt + 1;
    const uint32_t sb = smem_u32(sm);

    {
        const __nv_bfloat16* qh = Qh + ((size_t)bh*Nc + q0)*DHc;
        const __nv_bfloat16* ql = Ql + ((size_t)bh*Nc + q0)*DHc;
        #pragma unroll
        for (int i = tid; i < 1024; i += 256) {
            const int r = i >> 3, c = i & 7;
            *(uint4*)&sm[OQ_H + r*QS + c*8] = *(const uint4*)&qh[r*64 + c*8];
            *(uint4*)&sm[OQ_L + r*QS + c*8] = *(const uint4*)&ql[r*64 + c*8];
        }
    }

    const int g = lane >> 2;
    float m0 = -1e30f, m1 = -1e30f, l0 = 0.f, l1 = 0.f, t0 = 0.f, t1 = 0.f;
    float sacc[16][4];
    float oacc[8][4];
    #pragma unroll
    for (int nt = 0; nt < 8; nt++)
        #pragma unroll
        for (int v = 0; v < 4; v++) oacc[nt][v] = 0.f;

    for (int kt = 0; kt < ntk; kt++) {
        __syncthreads();
        {
            const __nv_bfloat16* kh = Kh + ((size_t)bh*Nc + kt*128)*DHc;
            const __nv_bfloat16* kl = Kl + ((size_t)bh*Nc + kt*128)*DHc;
            #pragma unroll
            for (int i = tid; i < 1024; i += 256) {
                const int r = i >> 3, c = i & 7;
                *(uint4*)&sm[OK_H + r*QS + c*8] = *(const uint4*)&kh[r*64 + c*8];
                *(uint4*)&sm[OK_L + r*QS + c*8] = *(const uint4*)&kl[r*64 + c*8];
            }
            #pragma unroll
            for (int i = tid; i < 1024; i += 256) {
                const int r = i >> 4, c = i & 15;
                const size_t ad = ((size_t)bh*DHc + r)*Nc + kt*128 + c*8;
                *(uint4*)&sm[OV_H + r*PS + c*8] = *(const uint4*)&Vth[ad];
                *(uint4*)&sm[OV_L + r*PS + c*8] = *(const uint4*)&Vtl[ad];
            }
        }
        __syncthreads();
        attn_S(sb, w, lane, sacc);
        if (kt == qt) {
            #pragma unroll
            for (int nt = 0; nt < 16; nt++) {
                const int c0 = nt*8 + (lane & 3)*2;
                if (c0     > 16*w + g)     sacc[nt][0] = -1e30f;
                if (c0 + 1 > 16*w + g)     sacc[nt][1] = -1e30f;
                if (c0     > 16*w + g + 8) sacc[nt][2] = -1e30f;
                if (c0 + 1 > 16*w + g + 8) sacc[nt][3] = -1e30f;
            }
        }
        // tile row max
        float mt0 = -1e30f, mt1 = -1e30f;
        #pragma unroll
        for (int nt = 0; nt < 16; nt++) {
            mt0 = fmaxf(mt0, fmaxf(sacc[nt][0], sacc[nt][1]));
            mt1 = fmaxf(mt1, fmaxf(sacc[nt][2], sacc[nt][3]));
        }
        mt0 = fmaxf(mt0, __shfl_xor_sync(0xffffffffu, mt0, 1));
        mt0 = fmaxf(mt0, __shfl_xor_sync(0xffffffffu, mt0, 2));
        mt1 = fmaxf(mt1, __shfl_xor_sync(0xffffffffu, mt1, 1));
        mt1 = fmaxf(mt1, __shfl_xor_sync(0xffffffffu, mt1, 2));
        const float mn0 = fmaxf(m0, mt0), mn1 = fmaxf(m1, mt1);
        const float sc0 = __expf(m0 - mn0), sc1 = __expf(m1 - mn1);

        // p (unnormalized), l/t partials, store p to smem split-bf16
        const int pr0 = 16*w + g, pr1 = pr0 + 8;
        float s0 = 0.f, s1 = 0.f, u0 = 0.f, u1 = 0.f;
        #pragma unroll
        for (int nt = 0; nt < 16; nt++) {
            const int c0 = nt*8 + (lane & 3)*2;
            const float p00 = __expf(sacc[nt][0]-mn0);
            const float p01 = __expf(sacc[nt][1]-mn0);
            const float p10 = __expf(sacc[nt][2]-mn1);
            const float p11 = __expf(sacc[nt][3]-mn1);
            s0 += p00 + p01;
            s1 += p10 + p11;
            u0 += p00*sacc[nt][0] + p01*sacc[nt][1];
            u1 += p10*sacc[nt][2] + p11*sacc[nt][3];
            __nv_bfloat162 lo0, lo1;
            __nv_bfloat162 hi0 = split2(p00, p01, lo0);
            __nv_bfloat162 hi1 = split2(p10, p11, lo1);
            *(__nv_bfloat162*)&sm[OP_H + pr0*PS + c0] = hi0;
            *(__nv_bfloat162*)&sm[OP_L + pr0*PS + c0] = lo0;
            *(__nv_bfloat162*)&sm[OP_H + pr1*PS + c0] = hi1;
            *(__nv_bfloat162*)&sm[OP_L + pr1*PS + c0] = lo1;
        }
        s0 += __shfl_xor_sync(0xffffffffu, s0, 1);
        s0 += __shfl_xor_sync(0xffffffffu, s0, 2);
        s1 += __shfl_xor_sync(0xffffffffu, s1, 1);
        s1 += __shfl_xor_sync(0xffffffffu, s1, 2);
        u0 += __shfl_xor_sync(0xffffffffu, u0, 1);
        u0 += __shfl_xor_sync(0xffffffffu, u0, 2);
        u1 += __shfl_xor_sync(0xffffffffu, u1, 1);
        u1 += __shfl_xor_sync(0xffffffffu, u1, 2);
        l0 = l0*sc0 + s0;  t0 = t0*sc0 + u0;  m0 = mn0;
        l1 = l1*sc1 + s1;  t1 = t1*sc1 + u1;  m1 = mn1;

        // rescale running O
        #pragma unroll
        for (int nt = 0; nt < 8; nt++) {
            oacc[nt][0] *= sc0; oacc[nt][1] *= sc0;
            oacc[nt][2] *= sc1; oacc[nt][3] *= sc1;
        }
        __syncthreads();

        // O += P @ V^T-tiles (np-pair interleave, distance-4 chains)
        #pragma unroll
        for (int ks = 0; ks < 8; ks++) {
            const int ar = 16*w + (lane & 7) + ((lane >> 3) & 1)*8;
            const int ac = ks*16 + (lane >> 4)*8;
            uint32_t ah[4], al[4];
            LDSM4(ah[0], ah[1], ah[2], ah[3], sb + (uint32_t)(OP_H + ar*PS + ac)*2);
            LDSM4(al[0], al[1], al[2], al[3], sb + (uint32_t)(OP_L + ar*PS + ac)*2);
            #pragma unroll
            for (int pp = 0; pp < 2; pp++) {
                const int np0 = 2*pp, np1 = 2*pp + 1;
                const int bc = ks*16 + ((lane >> 3) & 1)*8;
                const int brA = np0*16 + ((lane >> 4) & 1)*8 + (lane & 7);
                const int brB = np1*16 + ((lane >> 4) & 1)*8 + (lane & 7);
                uint32_t bAh[4], bAl[4], bBh[4], bBl[4];
                LDSM4(bAh[0], bAh[1], bAh[2], bAh[3], sb + (uint32_t)(OV_H + brA*PS + bc)*2);
                LDSM4(bAl[0], bAl[1], bAl[2], bAl[3], sb + (uint32_t)(OV_L + brA*PS + bc)*2);
                LDSM4(bBh[0], bBh[1], bBh[2], bBh[3], sb + (uint32_t)(OV_H + brB*PS + bc)*2);
                LDSM4(bBl[0], bBl[1], bBl[2], bBl[3], sb + (uint32_t)(OV_L + brB*PS + bc)*2);
                MMA16816(oacc[4*pp+0], ah, bAh[0], bAh[1]);
                MMA16816(oacc[4*pp+1], ah, bAh[2], bAh[3]);
                MMA16816(oacc[4*pp+2], ah, bBh[0], bBh[1]);
                MMA16816(oacc[4*pp+3], ah, bBh[2], bBh[3]);
                MMA16816(oacc[4*pp+0], ah, bAl[0], bAl[1]);
                MMA16816(oacc[4*pp+1], ah, bAl[2], bAl[3]);
                MMA16816(oacc[4*pp+2], ah, bBl[0], bBl[1]);
                MMA16816(oacc[4*pp+3], ah, bBl[2], bBl[3]);
                MMA16816(oacc[4*pp+0], al, bAh[0], bAh[1]);
                MMA16816(oacc[4*pp+1], al, bAh[2], bAh[3]);
                MMA16816(oacc[4*pp+2], al, bBh[0], bBh[1]);
                MMA16816(oacc[4*pp+3], al, bBh[2], bBh[3]);
            }
        }
    }

    // ---------------- epilogue ----------------
    const float il0 = 1.f / l0, il1 = 1.f / l1;
    const int b = bh >> 4, h = bh & 15;
    const int qg0 = q0 + 16*w + g, qg1 = qg0 + 8;
    if ((lane & 3) == 0) {
        ent[(size_t)bh*Nc + qg0] = m0 + __logf(l0) - t0*il0;
        ent[(size_t)bh*Nc + qg1] = m1 + __logf(l1) - t1*il1;
    }
    const float bg = bg2[0];
    const float gt0 = il0 / (1.f + __expf(-(gacc[(size_t)b*Nc + qg0] + bg)));
    const float gt1 = il1 / (1.f + __expf(-(gacc[(size_t)b*Nc + qg1] + bg)));
    #pragma unroll
    for (int nt = 0; nt < 8; nt++) {
        const int c = h*64 + nt*8 + (lane & 3)*2;
        const size_t a0 = ((size_t)(b*Nc + qg0))*Dc + c;
        const size_t a1 = ((size_t)(b*Nc + qg1))*Dc + c;
        __nv_bfloat162 lo0, lo1;
        __nv_bfloat162 hi0 = split2(oacc[nt][0]*gt0, oacc[nt][1]*gt0, lo0);
        __nv_bfloat162 hi1 = split2(oacc[nt][2]*gt1, oacc[nt][3]*gt1, lo1);
        *(__nv_bfloat162*)&AOh[a0] = hi0;
        *(__nv_bfloat162*)&AOl[a0] = lo0;
        *(__nv_bfloat162*)&AOh[a1] = hi1;
        *(__nv_bfloat162*)&AOl[a1] = lo1;
    }
}

// ---------------------------------------------------------------------------
extern "C" void kernel_launch(void* const* d_in, const int* in_sizes, int n_in,
                              void* d_out, int out_size)
{
    const float* x   = (const float*)d_in[0];
    const float* Wq  = (const float*)d_in[2];
    const float* bq  = (const float*)d_in[3];
    const float* Wk  = (const float*)d_in[4];
    const float* bk  = (const float*)d_in[5];
    const float* Wv  = (const float*)d_in[6];
    const float* bv  = (const float*)d_in[7];
    const float* Wg1 = (const float*)d_in[8];
    const float* bg1 = (const float*)d_in[9];
    const float* Wg2 = (const float*)d_in[10];
    const float* bg2 = (const float*)d_in[11];
    const float* Wo  = (const float*)d_in[12];
    const float* bo  = (const float*)d_in[13];

    float* out = (float*)d_out;                       // [B, N, D]
    float* ent = out + (size_t)Bc*Nc*Dc;              // [B, H, N]

    float *Gp;
    __nv_bfloat16 *xh, *xl, *qh, *ql, *kh, *kl, *vth, *vtl, *AOh, *AOl, *Wth, *Wtl;
    cudaGetSymbolAddress((void**)&Gp,  g_gacc);
    cudaGetSymbolAddress((void**)&xh,  g_xh);
    cudaGetSymbolAddress((void**)&xl,  g_xl);
    cudaGetSymbolAddress((void**)&qh,  g_qh);
    cudaGetSymbolAddress((void**)&ql,  g_ql);
    cudaGetSymbolAddress((void**)&kh,  g_kh);
    cudaGetSymbolAddress((void**)&kl,  g_kl);
    cudaGetSymbolAddress((void**)&vth, g_vth);
    cudaGetSymbolAddress((void**)&vtl, g_vtl);
    cudaGetSymbolAddress((void**)&AOh, g_AOh);
    cudaGetSymbolAddress((void**)&AOl, g_AOl);
    cudaGetSymbolAddress((void**)&Wth, g_Wth);
    cudaGetSymbolAddress((void**)&Wtl, g_Wtl);

    const int TCSMEM = 2 * 4 * 128 * KSTR * 2;     // 81920
    cudaFuncSetAttribute(proj_gemm, cudaFuncAttributeMaxDynamicSharedMemorySize, TCSMEM);
    cudaFuncSetAttribute(out_gemm,  cudaFuncAttributeMaxDynamicSharedMemorySize, TCSMEM);
    cudaFuncSetAttribute(attn_k, cudaFuncAttributeMaxDynamicSharedMemorySize, ATT_SMEM_B);

    zg_k<<<Mc/256, 256>>>(Gp);
    split_k<<<Mc*Dc/4/256, 256>>>(x, xh, xl, Mc*Dc/4);
    WPtrs wp; wp.w[0] = Wq; wp.w[1] = Wk; wp.w[2] = Wv; wp.w[3] = Wg1; wp.w[4] = Wo;
    tsplit_k<<<dim3(32, 32, 5), 256>>>(wp, Wth, Wtl);

    BPtrs bp; bp.b[0] = bq; bp.b[1] = bk; bp.b[2] = bv; bp.b[3] = bg1;
    proj_gemm<<<dim3(Dc/128, Mc/128, 4), 256, TCSMEM>>>(
        xh, xl, Wth, Wtl, bp, Wg2, Gp, qh, ql, kh, kl, vth, vtl);

    attn_k<<<dim3(Nc/128, BHc), 256, ATT_SMEM_B>>>(qh, ql, kh, kl, vth, vtl,
                                                   Gp, bg2, AOh, AOl, ent);

    out_gemm<<<dim3(Dc/128, Mc/128), 256, TCSMEM>>>(
        AOh, AOl, Wth + 4*(size_t)Dc*Dc, Wtl + 4*(size_t)Dc*Dc, bo, out);
}